// round 10
// baseline (speedup 1.0000x reference)
#include <cuda_runtime.h>
#include <math.h>

#define S_   1024
#define B_   2
#define D_   1024
#define NH   16
#define DH   64
#define DI_  4096
#define R_   2048
#define SB   (S_*B_)          // 2048
#define RB   (R_*B_)          // 4096
#define ND   (NH*DH)          // 1024
#define NHEADS (B_*NH)        // 32
#define KRR  1152             // kr rows actually consumed (max index 1087)

// ---------------- scratch (device globals; no allocation allowed) ----------------
__device__ float g_q   [SB*ND];
__device__ float g_k   [SB*ND];
__device__ float g_v   [SB*ND];
__device__ float g_kr  [RB*ND];
__device__ float g_ef  [SB*NH*2];
__device__ float g_vec [SB*ND];
__device__ float g_attn[SB*ND];
__device__ float g_x   [SB*ND];
__device__ float g_f   [SB*DI_];
__device__ float g_f2  [SB*ND];
__device__ float g_buf [SB*ND];

enum { EPI_NONE = 0, EPI_BIAS = 1, EPI_BIAS_GELU = 2, EPI_RES = 3 };

__device__ __forceinline__ float gelu_f(float x) {
    return 0.5f * x * (1.0f + erff(x * 0.7071067811865476f));
}

// ---------------- bf16 split helpers ----------------
__device__ __forceinline__ void split2(float x0, float x1, unsigned& hi, unsigned& lo) {
    unsigned h;
    asm("cvt.rn.bf16x2.f32 %0, %1, %2;" : "=r"(h) : "f"(x1), "f"(x0));
    float h0 = __uint_as_float(h << 16);
    float h1 = __uint_as_float(h & 0xffff0000u);
    float r0 = x0 - h0;
    float r1 = x1 - h1;
    unsigned l;
    asm("cvt.rn.bf16x2.f32 %0, %1, %2;" : "=r"(l) : "f"(r1), "f"(r0));
    hi = h; lo = l;
}

__device__ __forceinline__ void mma_bf16(float* c,
    unsigned a0, unsigned a1, unsigned a2, unsigned a3, unsigned b0, unsigned b1) {
    asm volatile(
        "mma.sync.aligned.m16n8k16.row.col.f32.bf16.bf16.f32 "
        "{%0,%1,%2,%3}, {%4,%5,%6,%7}, {%8,%9}, {%0,%1,%2,%3};\n"
        : "+f"(c[0]), "+f"(c[1]), "+f"(c[2]), "+f"(c[3])
        : "r"(a0), "r"(a1), "r"(a2), "r"(a3), "r"(b0), "r"(b1));
}

// ---------------- tensor-core 128x128 GEMM body, bf16 split, NN / NT ----------------
template<int EPI, bool TB>
__device__ __forceinline__ void tgemm_body(
    const float* __restrict__ A, const float* __restrict__ Bm, float* __restrict__ C,
    int M, int Nn, int K, const float* __restrict__ bias, const float* __restrict__ res,
    int m0, int n0)
{
    __shared__ unsigned Ah[2][8][136], Al[2][8][136];
    __shared__ unsigned Bh[2][8][136], Bl[2][8][136];
    const int tid = threadIdx.x;
    const int wid = tid >> 5, lane = tid & 31;
    const int wm = (wid >> 2) * 64;
    const int wn = (wid & 3) * 32;
    const int g  = lane >> 2;
    const int tg = lane & 3;

    const int lm = tid >> 1, lq = (tid & 1) * 8;
    const int bk = tid >> 5, bn = (tid & 31) * 4;

    float acc[4][4][4];
    #pragma unroll
    for (int mt = 0; mt < 4; mt++)
        #pragma unroll
        for (int nt = 0; nt < 4; nt++)
            #pragma unroll
            for (int r = 0; r < 4; r++) acc[mt][nt][r] = 0.f;

    float a_st[8], b_st[8];

    auto load_slab = [&](int k0) {
        *(float4*)(a_st)     = *(const float4*)(A + (size_t)(m0 + lm) * K + k0 + lq);
        *(float4*)(a_st + 4) = *(const float4*)(A + (size_t)(m0 + lm) * K + k0 + lq + 4);
        if (TB) {
            *(float4*)(b_st)     = *(const float4*)(Bm + (size_t)(n0 + lm) * K + k0 + lq);
            *(float4*)(b_st + 4) = *(const float4*)(Bm + (size_t)(n0 + lm) * K + k0 + lq + 4);
        } else {
            *(float4*)(b_st)     = *(const float4*)(Bm + (size_t)(k0 + 2 * bk) * Nn + n0 + bn);
            *(float4*)(b_st + 4) = *(const float4*)(Bm + (size_t)(k0 + 2 * bk + 1) * Nn + n0 + bn);
        }
    };

    auto store_slab = [&](int s) {
        #pragma unroll
        for (int j = 0; j < 4; j++) {
            unsigned hi, lo;
            split2(a_st[2 * j], a_st[2 * j + 1], hi, lo);
            Ah[s][(lq >> 1) + j][lm] = hi;
            Al[s][(lq >> 1) + j][lm] = lo;
        }
        if (TB) {
            #pragma unroll
            for (int j = 0; j < 4; j++) {
                unsigned hi, lo;
                split2(b_st[2 * j], b_st[2 * j + 1], hi, lo);
                Bh[s][(lq >> 1) + j][lm] = hi;
                Bl[s][(lq >> 1) + j][lm] = lo;
            }
        } else {
            #pragma unroll
            for (int j = 0; j < 4; j++) {
                unsigned hi, lo;
                split2(b_st[j], b_st[4 + j], hi, lo);
                Bh[s][bk][bn + j] = hi;
                Bl[s][bk][bn + j] = lo;
            }
        }
    };

    auto compute = [&](int s) {
        unsigned bh0[4], bh1[4], bl0[4], bl1[4];
        #pragma unroll
        for (int nt = 0; nt < 4; nt++) {
            int c = wn + nt * 8 + g;
            bh0[nt] = Bh[s][tg][c];     bh1[nt] = Bh[s][tg + 4][c];
            bl0[nt] = Bl[s][tg][c];     bl1[nt] = Bl[s][tg + 4][c];
        }
        #pragma unroll
        for (int mt = 0; mt < 4; mt++) {
            int r0c = wm + mt * 16 + g;
            unsigned ah0 = Ah[s][tg][r0c],     ah1 = Ah[s][tg][r0c + 8];
            unsigned ah2 = Ah[s][tg + 4][r0c], ah3 = Ah[s][tg + 4][r0c + 8];
            unsigned al0 = Al[s][tg][r0c],     al1 = Al[s][tg][r0c + 8];
            unsigned al2 = Al[s][tg + 4][r0c], al3 = Al[s][tg + 4][r0c + 8];
            #pragma unroll
            for (int nt = 0; nt < 4; nt++) {
                float* c = acc[mt][nt];
                mma_bf16(c, ah0, ah1, ah2, ah3, bh0[nt], bh1[nt]);
                mma_bf16(c, ah0, ah1, ah2, ah3, bl0[nt], bl1[nt]);
                mma_bf16(c, al0, al1, al2, al3, bh0[nt], bh1[nt]);
            }
        }
    };

    const int nslab = K >> 4;
    load_slab(0);
    store_slab(0);
    __syncthreads();
    for (int kt = 0; kt < nslab; kt++) {
        if (kt + 1 < nslab) load_slab((kt + 1) << 4);
        compute(kt & 1);
        if (kt + 1 < nslab) store_slab((kt + 1) & 1);
        __syncthreads();
    }

    #pragma unroll
    for (int mt = 0; mt < 4; mt++) {
        int r0 = m0 + wm + mt * 16 + g;
        #pragma unroll
        for (int nt = 0; nt < 4; nt++) {
            int c0 = n0 + wn + nt * 8 + tg * 2;
            #pragma unroll
            for (int r = 0; r < 4; r++) {
                int mm = r0 + (r >> 1) * 8;
                int nn = c0 + (r & 1);
                float v = acc[mt][nt][r];
                if (EPI == EPI_BIAS || EPI == EPI_BIAS_GELU) v += bias[nn];
                if (EPI == EPI_BIAS_GELU) v = gelu_f(v);
                if (EPI == EPI_RES) v += res[(size_t)mm * Nn + nn];
                C[(size_t)mm * Nn + nn] = v;
            }
        }
    }
}

// ---------------- 128x64-tile variant (for grid-underfilled N=1024 GEMMs) ----------------
template<int EPI, bool TB>
__device__ __forceinline__ void tgemm64_body(
    const float* __restrict__ A, const float* __restrict__ Bm, float* __restrict__ C,
    int M, int Nn, int K, const float* __restrict__ bias, const float* __restrict__ res,
    int m0, int n0)
{
    __shared__ unsigned Ah[2][8][136], Al[2][8][136];
    __shared__ unsigned Bh[2][8][72], Bl[2][8][72];
    const int tid = threadIdx.x;
    const int wid = tid >> 5, lane = tid & 31;
    const int wm = (wid >> 2) * 64;     // 0 or 64
    const int wn = (wid & 3) * 16;      // 0..48
    const int g  = lane >> 2;
    const int tg = lane & 3;

    const int lm = tid >> 1, lq = (tid & 1) * 8;      // A loader
    const int nr = tid >> 2, nq = (tid & 3) * 4;      // B NT loader (64 rows x 16 k)
    const int bk = tid >> 5, bn = (tid & 31) * 2;     // B NN loader (8 kpairs x 64 cols)

    float acc[4][2][4];
    #pragma unroll
    for (int mt = 0; mt < 4; mt++)
        #pragma unroll
        for (int nt = 0; nt < 2; nt++)
            #pragma unroll
            for (int r = 0; r < 4; r++) acc[mt][nt][r] = 0.f;

    float a_st[8], b_st[4];

    auto load_slab = [&](int k0) {
        *(float4*)(a_st)     = *(const float4*)(A + (size_t)(m0 + lm) * K + k0 + lq);
        *(float4*)(a_st + 4) = *(const float4*)(A + (size_t)(m0 + lm) * K + k0 + lq + 4);
        if (TB) {
            *(float4*)(b_st) = *(const float4*)(Bm + (size_t)(n0 + nr) * K + k0 + nq);
        } else {
            *(float2*)(b_st)     = *(const float2*)(Bm + (size_t)(k0 + 2 * bk) * Nn + n0 + bn);
            *(float2*)(b_st + 2) = *(const float2*)(Bm + (size_t)(k0 + 2 * bk + 1) * Nn + n0 + bn);
        }
    };

    auto store_slab = [&](int s) {
        #pragma unroll
        for (int j = 0; j < 4; j++) {
            unsigned hi, lo;
            split2(a_st[2 * j], a_st[2 * j + 1], hi, lo);
            Ah[s][(lq >> 1) + j][lm] = hi;
            Al[s][(lq >> 1) + j][lm] = lo;
        }
        if (TB) {
            #pragma unroll
            for (int j = 0; j < 2; j++) {
                unsigned hi, lo;
                split2(b_st[2 * j], b_st[2 * j + 1], hi, lo);
                Bh[s][(nq >> 1) + j][nr] = hi;
                Bl[s][(nq >> 1) + j][nr] = lo;
            }
        } else {
            #pragma unroll
            for (int j = 0; j < 2; j++) {
                unsigned hi, lo;
                split2(b_st[j], b_st[2 + j], hi, lo);
                Bh[s][bk][bn + j] = hi;
                Bl[s][bk][bn + j] = lo;
            }
        }
    };

    auto compute = [&](int s) {
        unsigned bh0[2], bh1[2], bl0[2], bl1[2];
        #pragma unroll
        for (int nt = 0; nt < 2; nt++) {
            int c = wn + nt * 8 + g;
            bh0[nt] = Bh[s][tg][c];     bh1[nt] = Bh[s][tg + 4][c];
            bl0[nt] = Bl[s][tg][c];     bl1[nt] = Bl[s][tg + 4][c];
        }
        #pragma unroll
        for (int mt = 0; mt < 4; mt++) {
            int r0c = wm + mt * 16 + g;
            unsigned ah0 = Ah[s][tg][r0c],     ah1 = Ah[s][tg][r0c + 8];
            unsigned ah2 = Ah[s][tg + 4][r0c], ah3 = Ah[s][tg + 4][r0c + 8];
            unsigned al0 = Al[s][tg][r0c],     al1 = Al[s][tg][r0c + 8];
            unsigned al2 = Al[s][tg + 4][r0c], al3 = Al[s][tg + 4][r0c + 8];
            #pragma unroll
            for (int nt = 0; nt < 2; nt++) {
                float* c = acc[mt][nt];
                mma_bf16(c, ah0, ah1, ah2, ah3, bh0[nt], bh1[nt]);
                mma_bf16(c, ah0, ah1, ah2, ah3, bl0[nt], bl1[nt]);
                mma_bf16(c, al0, al1, al2, al3, bh0[nt], bh1[nt]);
            }
        }
    };

    const int nslab = K >> 4;
    load_slab(0);
    store_slab(0);
    __syncthreads();
    for (int kt = 0; kt < nslab; kt++) {
        if (kt + 1 < nslab) load_slab((kt + 1) << 4);
        compute(kt & 1);
        if (kt + 1 < nslab) store_slab((kt + 1) & 1);
        __syncthreads();
    }

    #pragma unroll
    for (int mt = 0; mt < 4; mt++) {
        int r0 = m0 + wm + mt * 16 + g;
        #pragma unroll
        for (int nt = 0; nt < 2; nt++) {
            int c0 = n0 + wn + nt * 8 + tg * 2;
            #pragma unroll
            for (int r = 0; r < 4; r++) {
                int mm = r0 + (r >> 1) * 8;
                int nn = c0 + (r & 1);
                float v = acc[mt][nt][r];
                if (EPI == EPI_BIAS || EPI == EPI_BIAS_GELU) v += bias[nn];
                if (EPI == EPI_BIAS_GELU) v = gelu_f(v);
                if (EPI == EPI_RES) v += res[(size_t)mm * Nn + nn];
                C[(size_t)mm * Nn + nn] = v;
            }
        }
    }
}

template<int EPI, bool TB>
__global__ void __launch_bounds__(256, 2) tgemm(
    const float* __restrict__ A, const float* __restrict__ Bm, float* __restrict__ C,
    int M, int Nn, int K, const float* __restrict__ bias, const float* __restrict__ res)
{
    tgemm_body<EPI, TB>(A, Bm, C, M, Nn, K, bias, res, blockIdx.y * 128, blockIdx.x * 128);
}

template<int EPI, bool TB>
__global__ void __launch_bounds__(256, 2) tgemm64(
    const float* __restrict__ A, const float* __restrict__ Bm, float* __restrict__ C,
    int M, int Nn, int K, const float* __restrict__ bias, const float* __restrict__ res)
{
    tgemm64_body<EPI, TB>(A, Bm, C, M, Nn, K, bias, res, blockIdx.y * 128, blockIdx.x * 64);
}

// merged projections: Wr (blocks 0..143), then Q,K,V (blocks 144..527)
__global__ void __launch_bounds__(256, 2) proj_all(
    const float* __restrict__ A, const float* __restrict__ pos_emb,
    const float* __restrict__ Wq, const float* __restrict__ Wk,
    const float* __restrict__ Wv, const float* __restrict__ Wr,
    float* __restrict__ Cq, float* __restrict__ Ck, float* __restrict__ Cv,
    float* __restrict__ Ckr)
{
    int idx = blockIdx.x;
    if (idx < 144) {
        tgemm_body<EPI_NONE, false>(pos_emb, Wr, Ckr, KRR * B_, ND, D_, nullptr, nullptr,
                                    (idx >> 3) * 128, (idx & 7) * 128);
    } else {
        idx -= 144;
        int which = idx >> 7;     // 0..2
        int t = idx & 127;
        const float* Bm = (which == 0) ? Wq : (which == 1) ? Wk : Wv;
        float* C        = (which == 0) ? Cq : (which == 1) ? Ck : Cv;
        tgemm_body<EPI_NONE, false>(A, Bm, C, SB, ND, D_, nullptr, nullptr,
                                    (t >> 3) * 128, (t & 7) * 128);
    }
}

// ---------------- ef[i,b,n,s] = (q + r_s_bias) . seg_embed[s] ----------------
__global__ void ef_kernel(const float* __restrict__ q, const float* __restrict__ rs,
                          const float* __restrict__ se, float* __restrict__ ef)
{
    int w = blockIdx.x * 4 + (threadIdx.x >> 5);   // over SB*NH
    int lane = threadIdx.x & 31;
    int row = w / NH, n = w % NH;
    int d0 = lane * 2;
    const float* qp = q + (size_t)row * ND + n * DH;
    float q0 = qp[d0]     + rs[n * DH + d0];
    float q1 = qp[d0 + 1] + rs[n * DH + d0 + 1];
    float s0 = q0 * se[(0 * NH + n) * DH + d0] + q1 * se[(0 * NH + n) * DH + d0 + 1];
    float s1 = q0 * se[(1 * NH + n) * DH + d0] + q1 * se[(1 * NH + n) * DH + d0 + 1];
    #pragma unroll
    for (int off = 16; off; off >>= 1) {
        s0 += __shfl_xor_sync(0xffffffffu, s0, off);
        s1 += __shfl_xor_sync(0xffffffffu, s1, off);
    }
    if (lane == 0) { ef[w * 2] = s0; ef[w * 2 + 1] = s1; }
}

// ---------------- fused flash attention: score + online softmax + P@V ----------------
// CTA = (head, i-tile of 64 rows). 16 warps: rg = wid&3 (row group of 16),
// sub = wid>>2 (owns score cols sub*16..+15 == its P@V k16 chunk).
// Krs kept in a 128-col ring: kr row m lives at phys col 64 + (m & 127).
struct FlashSmem {
    unsigned QA[4][32][72];                 // Qw hi/lo, Qr hi/lo [kpair][row]
    union {
        unsigned KB[2][32][200];            // hi/lo [kpair][col: 0..63 K, 64..191 Krs ring]
        float    ored[64][68];              // final O reduction
    } kb;
    float dloc[64][132];                    // Dloc table (logical u = lj-li+64)
    unsigned VB[2][32][72];                 // V hi/lo [kpair(j)][d]
    float ef_s[64][2];
    float redmax[64][4];
    float redl[64][4];
};

__global__ void __launch_bounds__(512, 1) flash_attn(
    const float* __restrict__ q, const float* __restrict__ k, const float* __restrict__ kr,
    const float* __restrict__ v,
    const float* __restrict__ rw, const float* __restrict__ rr,
    const float* __restrict__ ef, const float* __restrict__ seg_mat,
    float* __restrict__ vec)
{
    extern __shared__ char smraw[];
    FlashSmem* sm = (FlashSmem*)smraw;
    const int head = blockIdx.x;
    const int b = head / NH, n = head % NH;
    const int i0 = (15 - blockIdx.y) * 64;      // longest-running CTAs first
    const int tid = threadIdx.x;
    const int wid = tid >> 5, lane = tid & 31;
    const int g = lane >> 2, tg = lane & 3;
    const int rg = wid & 3, sub = wid >> 2;
    const int rbase = rg * 16;

    // --- load Q once (Qw = q+rw, Qr = q+rr), split to bf16 hi/lo ---
    #pragma unroll
    for (int t = 0; t < 2; t++) {
        int job = tid + t * 512;
        int li = job >> 4, kq = (job & 15) * 4;
        const float* qp = q + ((size_t)((i0 + li) * B_ + b)) * ND + n * DH + kq;
        float4 qv = *(const float4*)qp;
        float4 wv = *(const float4*)(rw + n * DH + kq);
        float4 rv = *(const float4*)(rr + n * DH + kq);
        unsigned hi, lo; int kp = kq >> 1;
        split2(qv.x + wv.x, qv.y + wv.y, hi, lo); sm->QA[0][kp][li] = hi; sm->QA[1][kp][li] = lo;
        split2(qv.z + wv.z, qv.w + wv.w, hi, lo); sm->QA[0][kp+1][li] = hi; sm->QA[1][kp+1][li] = lo;
        split2(qv.x + rv.x, qv.y + rv.y, hi, lo); sm->QA[2][kp][li] = hi; sm->QA[3][kp][li] = lo;
        split2(qv.z + rv.z, qv.w + rv.w, hi, lo); sm->QA[2][kp+1][li] = hi; sm->QA[3][kp+1][li] = lo;
    }
    if (tid < 128)
        sm->ef_s[tid >> 1][tid & 1] =
            ef[((size_t)((i0 + (tid >> 1)) * B_ + b) * NH + n) * 2 + (tid & 1)];

    float m_r[2] = {-1e30f, -1e30f};
    float l_r[2] = {0.f, 0.f};
    float accO[8][4];
    #pragma unroll
    for (int f = 0; f < 8; f++)
        #pragma unroll
        for (int r = 0; r < 4; r++) accO[f][r] = 0.f;

    // loader index precompute
    const int lK_li = tid >> 4, lK_dq = (tid & 15) * 4;   // K/Krs loaders
    const int lV_jp = tid >> 4, lV_dq = (tid & 15) * 4;   // V loader

    for (int j0 = 0; j0 <= i0; j0 += 64) {
        const int w = S_ + j0 - i0 - 64;        // ring window start (mult of 64)
        const int ofs = w & 127;
        const bool first = (j0 == 0);
        __syncthreads();   // previous iteration consumers done

        // ===== issue ALL gmem loads first =====
        float4 kv0 = *(const float4*)(k + ((size_t)((j0 + lK_li) * B_ + b)) * ND + n * DH + lK_dq);
        float4 kv1 = *(const float4*)(k + ((size_t)((j0 + lK_li + 32) * B_ + b)) * ND + n * DH + lK_dq);
        const float* vp0 = v + ((size_t)((j0 + 2 * lV_jp) * B_ + b)) * ND + n * DH + lV_dq;
        float4 vv0 = *(const float4*)vp0;
        float4 vv1 = *(const float4*)(vp0 + (size_t)B_ * ND);
        const int mstart = first ? w : (w + 64);
        float4 rv0 = *(const float4*)(kr + ((size_t)((mstart + lK_li) * B_ + b)) * ND + n * DH + lK_dq);
        float4 rv1 = *(const float4*)(kr + ((size_t)((mstart + lK_li + 32) * B_ + b)) * ND + n * DH + lK_dq);
        float4 rv2, rv3;
        if (first) {
            rv2 = *(const float4*)(kr + ((size_t)((mstart + lK_li + 64) * B_ + b)) * ND + n * DH + lK_dq);
            rv3 = *(const float4*)(kr + ((size_t)((mstart + lK_li + 96) * B_ + b)) * ND + n * DH + lK_dq);
        }
        // seg_mat prefetch for this warp's 8 score elems
        float segv[2][4];
        #pragma unroll
        for (int fa = 0; fa < 2; fa++)
            #pragma unroll
            for (int r = 0; r < 4; r++) {
                int gi = i0 + rbase + g + (r >> 1) * 8;
                int gj = j0 + sub * 16 + fa * 8 + tg * 2 + (r & 1);
                segv[fa][r] = __ldg(&seg_mat[(((size_t)gi * S_ + gj) * B_ + b) * 2 + 1]);
            }

        // ===== split + store =====
        {
            unsigned hi, lo; int kp = lK_dq >> 1;
            split2(kv0.x, kv0.y, hi, lo); sm->kb.KB[0][kp][lK_li] = hi; sm->kb.KB[1][kp][lK_li] = lo;
            split2(kv0.z, kv0.w, hi, lo); sm->kb.KB[0][kp+1][lK_li] = hi; sm->kb.KB[1][kp+1][lK_li] = lo;
            split2(kv1.x, kv1.y, hi, lo); sm->kb.KB[0][kp][lK_li + 32] = hi; sm->kb.KB[1][kp][lK_li + 32] = lo;
            split2(kv1.z, kv1.w, hi, lo); sm->kb.KB[0][kp+1][lK_li + 32] = hi; sm->kb.KB[1][kp+1][lK_li + 32] = lo;
            int c0 = 64 + ((mstart + lK_li) & 127);
            int c1 = 64 + ((mstart + lK_li + 32) & 127);
            split2(rv0.x, rv0.y, hi, lo); sm->kb.KB[0][kp][c0] = hi; sm->kb.KB[1][kp][c0] = lo;
            split2(rv0.z, rv0.w, hi, lo); sm->kb.KB[0][kp+1][c0] = hi; sm->kb.KB[1][kp+1][c0] = lo;
            split2(rv1.x, rv1.y, hi, lo); sm->kb.KB[0][kp][c1] = hi; sm->kb.KB[1][kp][c1] = lo;
            split2(rv1.z, rv1.w, hi, lo); sm->kb.KB[0][kp+1][c1] = hi; sm->kb.KB[1][kp+1][c1] = lo;
            if (first) {
                int c2 = 64 + ((mstart + lK_li + 64) & 127);
                int c3 = 64 + ((mstart + lK_li + 96) & 127);
                split2(rv2.x, rv2.y, hi, lo); sm->kb.KB[0][kp][c2] = hi; sm->kb.KB[1][kp][c2] = lo;
                split2(rv2.z, rv2.w, hi, lo); sm->kb.KB[0][kp+1][c2] = hi; sm->kb.KB[1][kp+1][c2] = lo;
                split2(rv3.x, rv3.y, hi, lo); sm->kb.KB[0][kp][c3] = hi; sm->kb.KB[1][kp][c3] = lo;
                split2(rv3.z, rv3.w, hi, lo); sm->kb.KB[0][kp+1][c3] = hi; sm->kb.KB[1][kp+1][c3] = lo;
            }
            split2(vv0.x, vv1.x, hi, lo); sm->VB[0][lV_jp][lV_dq]     = hi; sm->VB[1][lV_jp][lV_dq]     = lo;
            split2(vv0.y, vv1.y, hi, lo); sm->VB[0][lV_jp][lV_dq + 1] = hi; sm->VB[1][lV_jp][lV_dq + 1] = lo;
            split2(vv0.z, vv1.z, hi, lo); sm->VB[0][lV_jp][lV_dq + 2] = hi; sm->VB[1][lV_jp][lV_dq + 2] = lo;
            split2(vv0.w, vv1.w, hi, lo); sm->VB[0][lV_jp][lV_dq + 3] = hi; sm->VB[1][lV_jp][lV_dq + 3] = lo;
        }
        __syncthreads();

        // --- score MMAs: ac (2 frags) + Dloc (4 frags) ---
        float aS[2][4], dS[4][4];
        #pragma unroll
        for (int f = 0; f < 2; f++)
            #pragma unroll
            for (int r = 0; r < 4; r++) aS[f][r] = 0.f;
        #pragma unroll
        for (int f = 0; f < 4; f++)
            #pragma unroll
            for (int r = 0; r < 4; r++) dS[f][r] = 0.f;

        #pragma unroll
        for (int kf = 0; kf < 4; kf++) {
            int kp = kf * 8;
            unsigned wh0 = sm->QA[0][kp + tg][rbase + g],     wh1 = sm->QA[0][kp + tg][rbase + g + 8];
            unsigned wh2 = sm->QA[0][kp + tg + 4][rbase + g], wh3 = sm->QA[0][kp + tg + 4][rbase + g + 8];
            unsigned wl0 = sm->QA[1][kp + tg][rbase + g],     wl1 = sm->QA[1][kp + tg][rbase + g + 8];
            unsigned wl2 = sm->QA[1][kp + tg + 4][rbase + g], wl3 = sm->QA[1][kp + tg + 4][rbase + g + 8];
            #pragma unroll
            for (int fa = 0; fa < 2; fa++) {
                int c = (sub * 2 + fa) * 8 + g;
                unsigned bh0 = sm->kb.KB[0][kp + tg][c], bh1 = sm->kb.KB[0][kp + tg + 4][c];
                unsigned bl0 = sm->kb.KB[1][kp + tg][c], bl1 = sm->kb.KB[1][kp + tg + 4][c];
                mma_bf16(aS[fa], wh0, wh1, wh2, wh3, bh0, bh1);
                mma_bf16(aS[fa], wh0, wh1, wh2, wh3, bl0, bl1);
                mma_bf16(aS[fa], wl0, wl1, wl2, wl3, bh0, bh1);
            }
            unsigned rh0 = sm->QA[2][kp + tg][rbase + g],     rh1 = sm->QA[2][kp + tg][rbase + g + 8];
            unsigned rh2 = sm->QA[2][kp + tg + 4][rbase + g], rh3 = sm->QA[2][kp + tg + 4][rbase + g + 8];
            unsigned rl0 = sm->QA[3][kp + tg][rbase + g],     rl1 = sm->QA[3][kp + tg][rbase + g + 8];
            unsigned rl2 = sm->QA[3][kp + tg + 4][rbase + g], rl3 = sm->QA[3][kp + tg + 4][rbase + g + 8];
            #pragma unroll
            for (int fd = 0; fd < 4; fd++) {
                int c = 64 + ((ofs + sub * 32 + fd * 8) & 127) + g;
                unsigned bh0 = sm->kb.KB[0][kp + tg][c], bh1 = sm->kb.KB[0][kp + tg + 4][c];
                unsigned bl0 = sm->kb.KB[1][kp + tg][c], bl1 = sm->kb.KB[1][kp + tg + 4][c];
                mma_bf16(dS[fd], rh0, rh1, rh2, rh3, bh0, bh1);
                mma_bf16(dS[fd], rh0, rh1, rh2, rh3, bl0, bl1);
                mma_bf16(dS[fd], rl0, rl1, rl2, rl3, bh0, bh1);
            }
        }
        // dump own Dloc frags (logical u index)
        #pragma unroll
        for (int fd = 0; fd < 4; fd++)
            #pragma unroll
            for (int r = 0; r < 4; r++)
                sm->dloc[rbase + g + (r >> 1) * 8][sub * 32 + fd * 8 + tg * 2 + (r & 1)] = dS[fd][r];
        __syncthreads();

        // --- combine + warp row max ---
        float s_v[2][4];
        float wmax[2] = {-3.0e38f, -3.0e38f};
        const bool diag = (j0 == i0);
        #pragma unroll
        for (int fa = 0; fa < 2; fa++)
            #pragma unroll
            for (int r = 0; r < 4; r++) {
                int li = rbase + g + (r >> 1) * 8;
                int lj = sub * 16 + fa * 8 + tg * 2 + (r & 1);
                float val;
                if (diag && lj > li) {
                    val = -1e30f;
                } else {
                    float dl = sm->dloc[li][lj - li + 64];
                    float e0 = sm->ef_s[li][0], e1 = sm->ef_s[li][1];
                    val = (aS[fa][r] + dl + e0 + segv[fa][r] * (e1 - e0)) * 0.125f;
                }
                s_v[fa][r] = val;
                wmax[r >> 1] = fmaxf(wmax[r >> 1], val);
            }
        #pragma unroll
        for (int hh = 0; hh < 2; hh++) {
            wmax[hh] = fmaxf(wmax[hh], __shfl_xor_sync(0xffffffffu, wmax[hh], 1));
            wmax[hh] = fmaxf(wmax[hh], __shfl_xor_sync(0xffffffffu, wmax[hh], 2));
        }
        if (tg == 0) {
            sm->redmax[rbase + g][sub]     = wmax[0];
            sm->redmax[rbase + g + 8][sub] = wmax[1];
        }
        __syncthreads();

        // --- online softmax update ---
        float alpha_h[2];
        #pragma unroll
        for (int hh = 0; hh < 2; hh++) {
            int li = rbase + g + hh * 8;
            float tm = fmaxf(fmaxf(sm->redmax[li][0], sm->redmax[li][1]),
                             fmaxf(sm->redmax[li][2], sm->redmax[li][3]));
            float mnew = fmaxf(m_r[hh], tm);
            alpha_h[hh] = __expf(m_r[hh] - mnew);
            m_r[hh] = mnew;
            l_r[hh] *= alpha_h[hh];
        }
        #pragma unroll
        for (int f = 0; f < 8; f++) {
            accO[f][0] *= alpha_h[0]; accO[f][1] *= alpha_h[0];
            accO[f][2] *= alpha_h[1]; accO[f][3] *= alpha_h[1];
        }
        // --- P = exp(s - m), row partial sums, pack A-frags in-register ---
        float pv[2][4];
        float psum[2] = {0.f, 0.f};
        #pragma unroll
        for (int fa = 0; fa < 2; fa++)
            #pragma unroll
            for (int r = 0; r < 4; r++) {
                float p = __expf(s_v[fa][r] - m_r[r >> 1]);
                pv[fa][r] = p;
                psum[r >> 1] += p;
            }
        #pragma unroll
        for (int hh = 0; hh < 2; hh++) {
            psum[hh] += __shfl_xor_sync(0xffffffffu, psum[hh], 1);
            psum[hh] += __shfl_xor_sync(0xffffffffu, psum[hh], 2);
            l_r[hh] += psum[hh];
        }
        unsigned ph[4], pl[4];
        split2(pv[0][0], pv[0][1], ph[0], pl[0]);
        split2(pv[0][2], pv[0][3], ph[1], pl[1]);
        split2(pv[1][0], pv[1][1], ph[2], pl[2]);
        split2(pv[1][2], pv[1][3], ph[3], pl[3]);
        // --- P @ V (this warp's k16 chunk = V rows sub*16..+15) ---
        const int kpb = sub * 8;
        #pragma unroll
        for (int f = 0; f < 8; f++) {
            int c = f * 8 + g;
            unsigned bh0 = sm->VB[0][kpb + tg][c], bh1 = sm->VB[0][kpb + tg + 4][c];
            unsigned bl0 = sm->VB[1][kpb + tg][c], bl1 = sm->VB[1][kpb + tg + 4][c];
            mma_bf16(accO[f], ph[0], ph[1], ph[2], ph[3], bh0, bh1);
            mma_bf16(accO[f], ph[0], ph[1], ph[2], ph[3], bl0, bl1);
            mma_bf16(accO[f], pl[0], pl[1], pl[2], pl[3], bh0, bh1);
        }
    }

    // --- final: reduce K-split partials deterministically, normalize, store ---
    __syncthreads();
    if (tg == 0) {
        sm->redl[rbase + g][sub]     = l_r[0];
        sm->redl[rbase + g + 8][sub] = l_r[1];
    }
    #pragma unroll
    for (int s = 0; s < 4; s++) {
        if (sub == s) {
            #pragma unroll
            for (int f = 0; f < 8; f++)
                #pragma unroll
                for (int r = 0; r < 4; r++) {
                    int row = rbase + g + (r >> 1) * 8;
                    int col = f * 8 + tg * 2 + (r & 1);
                    if (s == 0) sm->kb.ored[row][col] = accO[f][r];
                    else        sm->kb.ored[row][col] += accO[f][r];
                }
        }
        __syncthreads();
    }
    #pragma unroll
    for (int t = 0; t < 8; t++) {
        int job = tid + t * 512;
        int row = job >> 6, col = job & 63;
        float lt = sm->redl[row][0] + sm->redl[row][1] + sm->redl[row][2] + sm->redl[row][3];
        vec[((size_t)((i0 + row) * B_ + b)) * ND + n * DH + col] = sm->kb.ored[row][col] / lt;
    }
}

// ---------------- layernorm (optional fused residual add) ----------------
__global__ void ln_kernel(const float* __restrict__ x, const float* __restrict__ res,
                          const float* __restrict__ g, const float* __restrict__ b,
                          float* __restrict__ out)
{
    __shared__ float red[256];
    const int row = blockIdx.x, tid = threadIdx.x;
    const float* xr = x + (size_t)row * D_;
    float v[4];
    float s = 0.f;
    #pragma unroll
    for (int t = 0; t < 4; t++) {
        int d = tid + t * 256;
        v[t] = xr[d];
        if (res) v[t] += res[(size_t)row * D_ + d];
        s += v[t];
    }
    red[tid] = s; __syncthreads();
    for (int o = 128; o > 0; o >>= 1) { if (tid < o) red[tid] += red[tid + o]; __syncthreads(); }
    float mean = red[0] * (1.f / D_);
    __syncthreads();
    s = 0.f;
    #pragma unroll
    for (int t = 0; t < 4; t++) { float d2 = v[t] - mean; s += d2 * d2; }
    red[tid] = s; __syncthreads();
    for (int o = 128; o > 0; o >>= 1) { if (tid < o) red[tid] += red[tid + o]; __syncthreads(); }
    float inv = rsqrtf(red[0] * (1.f / D_) + 1e-12f);
    #pragma unroll
    for (int t = 0; t < 4; t++) {
        int d = tid + t * 256;
        out[(size_t)row * D_ + d] = (v[t] - mean) * inv * g[d] + b[d];
    }
}

// ---------------- host ----------------
static float* sym_addr(const void* sym) {
    void* p = nullptr;
    cudaGetSymbolAddress(&p, sym);
    return (float*)p;
}

extern "C" void kernel_launch(void* const* d_in, const int* in_sizes, int n_in,
                              void* d_out, int out_size)
{
    (void)in_sizes; (void)n_in; (void)out_size;
    const float* h         = (const float*)d_in[0];
    const float* pos_emb   = (const float*)d_in[1];
    const float* seg_mat   = (const float*)d_in[3];
    const float* Wq        = (const float*)d_in[4];
    const float* Wk        = (const float*)d_in[5];
    const float* Wv        = (const float*)d_in[6];
    const float* Wo        = (const float*)d_in[7];
    const float* Wr        = (const float*)d_in[8];
    const float* rw        = (const float*)d_in[9];
    const float* rr        = (const float*)d_in[10];
    const float* rs        = (const float*)d_in[11];
    const float* se        = (const float*)d_in[12];
    const float* ln1g      = (const float*)d_in[13];
    const float* ln1b      = (const float*)d_in[14];
    const float* w1        = (const float*)d_in[15];
    const float* b1        = (const float*)d_in[16];
    const float* w2        = (const float*)d_in[17];
    const float* b2        = (const float*)d_in[18];
    const float* ln2g      = (const float*)d_in[19];
    const float* ln2b      = (const float*)d_in[20];
    float* out = (float*)d_out;

    float* gq    = sym_addr(g_q);
    float* gk    = sym_addr(g_k);
    float* gv    = sym_addr(g_v);
    float* gkr   = sym_addr(g_kr);
    float* gef   = sym_addr(g_ef);
    float* gvec  = sym_addr(g_vec);
    float* gattn = sym_addr(g_attn);
    float* gx    = sym_addr(g_x);
    float* gf    = sym_addr(g_f);
    float* gf2   = sym_addr(g_f2);
    float* gbuf  = sym_addr(g_buf);

    static bool attr_set = false;
    if (!attr_set) {
        cudaFuncSetAttribute(flash_attn, cudaFuncAttributeMaxDynamicSharedMemorySize,
                             (int)sizeof(FlashSmem));
        attr_set = true;
    }

    for (int l = 0; l < 2; l++) {
        const float* cur = (l == 0) ? h : gbuf;
        float* nxt = (l == 0) ? gbuf : out;
        const size_t woff = (size_t)l * D_ * ND;

        proj_all<<<144 + 384, 256>>>(
            cur, pos_emb, Wq + woff, Wk + woff, Wv + woff, Wr + woff,
            gq, gk, gv, gkr);

        ef_kernel<<<SB * NH / 4, 128>>>(gq, rs + l * NH * DH, se + l * 2 * NH * DH, gef);

        flash_attn<<<dim3(NHEADS, S_ / 64), 512, sizeof(FlashSmem)>>>(
            gq, gk, gkr, gv, rw + l * NH * DH, rr + l * NH * DH,
            gef, seg_mat, gvec);

        tgemm64<EPI_RES, true><<<dim3(D_ / 64, SB / 128), 256>>>(
            gvec, Wo + woff, gattn, SB, D_, ND, nullptr, cur);

        ln_kernel<<<SB, 256>>>(gattn, nullptr, ln1g + l * D_, ln1b + l * D_, gx);

        tgemm<EPI_BIAS_GELU, false><<<dim3(DI_ / 128, SB / 128), 256>>>(
            gx, w1 + (size_t)l * D_ * DI_, gf, SB, DI_, D_, b1 + l * DI_, nullptr);

        tgemm64<EPI_BIAS, false><<<dim3(D_ / 64, SB / 128), 256>>>(
            gf, w2 + (size_t)l * DI_ * D_, gf2, SB, D_, DI_, b2 + l * D_, nullptr);

        ln_kernel<<<SB, 256>>>(gf2, gx, ln2g + l * D_, ln2b + l * D_, nxt);
    }
}

// round 11
// speedup vs baseline: 1.0571x; 1.0571x over previous
#include <cuda_runtime.h>
#include <math.h>

#define S_   1024
#define B_   2
#define D_   1024
#define NH   16
#define DH   64
#define DI_  4096
#define R_   2048
#define SB   (S_*B_)          // 2048
#define RB   (R_*B_)          // 4096
#define ND   (NH*DH)          // 1024
#define NHEADS (B_*NH)        // 32
#define KRR  1152             // kr rows actually consumed (max index 1087)

// ---------------- scratch (device globals; no allocation allowed) ----------------
__device__ float g_q   [SB*ND];
__device__ float g_k   [SB*ND];
__device__ float g_v   [SB*ND];
__device__ float g_kr  [RB*ND];
__device__ float g_ef  [SB*NH*2];
__device__ float g_vec [SB*ND];
__device__ float g_attn[SB*ND];
__device__ float g_x   [SB*ND];
__device__ float g_f   [SB*DI_];
__device__ float g_f2  [SB*ND];
__device__ float g_buf [SB*ND];

enum { EPI_NONE = 0, EPI_BIAS = 1, EPI_BIAS_GELU = 2, EPI_RES = 3 };

__device__ __forceinline__ float gelu_f(float x) {
    return 0.5f * x * (1.0f + erff(x * 0.7071067811865476f));
}

// ---------------- bf16 split helpers ----------------
__device__ __forceinline__ void split2(float x0, float x1, unsigned& hi, unsigned& lo) {
    unsigned h;
    asm("cvt.rn.bf16x2.f32 %0, %1, %2;" : "=r"(h) : "f"(x1), "f"(x0));
    float h0 = __uint_as_float(h << 16);
    float h1 = __uint_as_float(h & 0xffff0000u);
    float r0 = x0 - h0;
    float r1 = x1 - h1;
    unsigned l;
    asm("cvt.rn.bf16x2.f32 %0, %1, %2;" : "=r"(l) : "f"(r1), "f"(r0));
    hi = h; lo = l;
}

__device__ __forceinline__ void mma_bf16(float* c,
    unsigned a0, unsigned a1, unsigned a2, unsigned a3, unsigned b0, unsigned b1) {
    asm volatile(
        "mma.sync.aligned.m16n8k16.row.col.f32.bf16.bf16.f32 "
        "{%0,%1,%2,%3}, {%4,%5,%6,%7}, {%8,%9}, {%0,%1,%2,%3};\n"
        : "+f"(c[0]), "+f"(c[1]), "+f"(c[2]), "+f"(c[3])
        : "r"(a0), "r"(a1), "r"(a2), "r"(a3), "r"(b0), "r"(b1));
}

// ---------------- cp.async helpers ----------------
__device__ __forceinline__ void cp16(void* smem, const void* g) {
    unsigned s = (unsigned)__cvta_generic_to_shared(smem);
    asm volatile("cp.async.cg.shared.global [%0], [%1], 16;" :: "r"(s), "l"(g));
}
__device__ __forceinline__ void cp_commit() {
    asm volatile("cp.async.commit_group;");
}
template<int N>
__device__ __forceinline__ void cp_wait() {
    asm volatile("cp.async.wait_group %0;" :: "n"(N));
}

// ---------------- GEMM shared memory (dynamic) ----------------
struct GemmSmem {
    float fA[2][128][16];        // fp32 staging for A (granule-swizzled)
    float fB[2][16 * 128];       // fp32 staging for B (NN: [k][n]; TB: [n][16] swizzled)
    unsigned Ah[8][136], Al[8][136];   // bf16 hi/lo, single stage
    unsigned Bh[8][136], Bl[8][136];
};

// ---------------- tensor-core 128x128 GEMM body, bf16 split, cp.async depth-2 ----------------
template<int EPI, bool TB>
__device__ __forceinline__ void tgemm_body(
    const float* __restrict__ A, const float* __restrict__ Bm, float* __restrict__ C,
    int M, int Nn, int K, const float* __restrict__ bias, const float* __restrict__ res,
    int m0, int n0)
{
    extern __shared__ char gsm_raw[];
    GemmSmem* sm = (GemmSmem*)gsm_raw;
    const int tid = threadIdx.x;
    const int wid = tid >> 5, lane = tid & 31;
    const int wm = (wid >> 2) * 64;
    const int wn = (wid & 3) * 32;
    const int g  = lane >> 2;
    const int tg = lane & 3;

    const int lm = tid >> 1, lq = (tid & 1) * 8;
    const int gq = lq >> 2;                 // 0 or 2
    const int bsw = (lm >> 1) & 1;          // granule swizzle bit
    const int pg0 = ((gq + bsw) & 3) * 4;
    const int pg1 = ((gq + 1 + bsw) & 3) * 4;
    const int bk = tid >> 5, bn = (tid & 31) * 4;

    float acc[4][4][4];
    #pragma unroll
    for (int mt = 0; mt < 4; mt++)
        #pragma unroll
        for (int nt = 0; nt < 4; nt++)
            #pragma unroll
            for (int r = 0; r < 4; r++) acc[mt][nt][r] = 0.f;

    auto cp_slab = [&](int k0, int st) {
        const float* gA = A + (size_t)(m0 + lm) * K + k0 + lq;
        float* sA = &sm->fA[st][lm][0];
        cp16(sA + pg0, gA);
        cp16(sA + pg1, gA + 4);
        if (TB) {
            const float* gB = Bm + (size_t)(n0 + lm) * K + k0 + lq;
            float* sB = &sm->fB[st][lm * 16];
            cp16(sB + pg0, gB);
            cp16(sB + pg1, gB + 4);
        } else {
            cp16(&sm->fB[st][(2 * bk) * 128 + bn],
                 Bm + (size_t)(k0 + 2 * bk) * Nn + n0 + bn);
            cp16(&sm->fB[st][(2 * bk + 1) * 128 + bn],
                 Bm + (size_t)(k0 + 2 * bk + 1) * Nn + n0 + bn);
        }
    };

    auto split_slab = [&](int st) {
        float a[8];
        const float* sA = &sm->fA[st][lm][0];
        *(float4*)(a)     = *(const float4*)(sA + pg0);
        *(float4*)(a + 4) = *(const float4*)(sA + pg1);
        #pragma unroll
        for (int j = 0; j < 4; j++) {
            unsigned hi, lo;
            split2(a[2 * j], a[2 * j + 1], hi, lo);
            sm->Ah[(lq >> 1) + j][lm] = hi;
            sm->Al[(lq >> 1) + j][lm] = lo;
        }
        if (TB) {
            float b[8];
            const float* sB = &sm->fB[st][lm * 16];
            *(float4*)(b)     = *(const float4*)(sB + pg0);
            *(float4*)(b + 4) = *(const float4*)(sB + pg1);
            #pragma unroll
            for (int j = 0; j < 4; j++) {
                unsigned hi, lo;
                split2(b[2 * j], b[2 * j + 1], hi, lo);
                sm->Bh[(lq >> 1) + j][lm] = hi;
                sm->Bl[(lq >> 1) + j][lm] = lo;
            }
        } else {
            float b[8];
            *(float4*)(b)     = *(const float4*)&sm->fB[st][(2 * bk) * 128 + bn];
            *(float4*)(b + 4) = *(const float4*)&sm->fB[st][(2 * bk + 1) * 128 + bn];
            #pragma unroll
            for (int j = 0; j < 4; j++) {
                unsigned hi, lo;
                split2(b[j], b[4 + j], hi, lo);
                sm->Bh[bk][bn + j] = hi;
                sm->Bl[bk][bn + j] = lo;
            }
        }
    };

    auto compute = [&]() {
        unsigned bh0[4], bh1[4], bl0[4], bl1[4];
        #pragma unroll
        for (int nt = 0; nt < 4; nt++) {
            int c = wn + nt * 8 + g;
            bh0[nt] = sm->Bh[tg][c];     bh1[nt] = sm->Bh[tg + 4][c];
            bl0[nt] = sm->Bl[tg][c];     bl1[nt] = sm->Bl[tg + 4][c];
        }
        #pragma unroll
        for (int mt = 0; mt < 4; mt++) {
            int r0c = wm + mt * 16 + g;
            unsigned ah0 = sm->Ah[tg][r0c],     ah1 = sm->Ah[tg][r0c + 8];
            unsigned ah2 = sm->Ah[tg + 4][r0c], ah3 = sm->Ah[tg + 4][r0c + 8];
            unsigned al0 = sm->Al[tg][r0c],     al1 = sm->Al[tg][r0c + 8];
            unsigned al2 = sm->Al[tg + 4][r0c], al3 = sm->Al[tg + 4][r0c + 8];
            #pragma unroll
            for (int nt = 0; nt < 4; nt++) {
                float* c = acc[mt][nt];
                mma_bf16(c, ah0, ah1, ah2, ah3, bh0[nt], bh1[nt]);
                mma_bf16(c, ah0, ah1, ah2, ah3, bl0[nt], bl1[nt]);
                mma_bf16(c, al0, al1, al2, al3, bh0[nt], bh1[nt]);
            }
        }
    };

    const int nslab = K >> 4;   // >= 2 always here (K = 1024 or 4096)
    cp_slab(0, 0);  cp_commit();
    cp_slab(16, 1); cp_commit();
    cp_wait<1>();               // slab 0 landed
    split_slab(0);
    __syncthreads();

    for (int kt = 0; kt < nslab; kt++) {
        if (kt + 2 < nslab) { cp_slab((kt + 2) << 4, kt & 1); cp_commit(); }
        compute();              // consumes bf16 arrays (slab kt)
        __syncthreads();
        if (kt + 1 < nslab) {
            if (kt + 2 < nslab) cp_wait<1>(); else cp_wait<0>();
            split_slab((kt + 1) & 1);
            __syncthreads();
        }
    }

    #pragma unroll
    for (int mt = 0; mt < 4; mt++) {
        int r0 = m0 + wm + mt * 16 + g;
        #pragma unroll
        for (int nt = 0; nt < 4; nt++) {
            int c0 = n0 + wn + nt * 8 + tg * 2;
            #pragma unroll
            for (int r = 0; r < 4; r++) {
                int mm = r0 + (r >> 1) * 8;
                int nn = c0 + (r & 1);
                float v = acc[mt][nt][r];
                if (EPI == EPI_BIAS || EPI == EPI_BIAS_GELU) v += bias[nn];
                if (EPI == EPI_BIAS_GELU) v = gelu_f(v);
                if (EPI == EPI_RES) v += res[(size_t)mm * Nn + nn];
                C[(size_t)mm * Nn + nn] = v;
            }
        }
    }
}

template<int EPI, bool TB>
__global__ void __launch_bounds__(256, 2) tgemm(
    const float* __restrict__ A, const float* __restrict__ Bm, float* __restrict__ C,
    int M, int Nn, int K, const float* __restrict__ bias, const float* __restrict__ res)
{
    tgemm_body<EPI, TB>(A, Bm, C, M, Nn, K, bias, res, blockIdx.y * 128, blockIdx.x * 128);
}

// merged projections: Wr (blocks 0..143), then Q,K,V (blocks 144..527)
__global__ void __launch_bounds__(256, 2) proj_all(
    const float* __restrict__ A, const float* __restrict__ pos_emb,
    const float* __restrict__ Wq, const float* __restrict__ Wk,
    const float* __restrict__ Wv, const float* __restrict__ Wr,
    float* __restrict__ Cq, float* __restrict__ Ck, float* __restrict__ Cv,
    float* __restrict__ Ckr)
{
    int idx = blockIdx.x;
    if (idx < 144) {
        tgemm_body<EPI_NONE, false>(pos_emb, Wr, Ckr, KRR * B_, ND, D_, nullptr, nullptr,
                                    (idx >> 3) * 128, (idx & 7) * 128);
    } else {
        idx -= 144;
        int which = idx >> 7;     // 0..2
        int t = idx & 127;
        const float* Bm = (which == 0) ? Wq : (which == 1) ? Wk : Wv;
        float* C        = (which == 0) ? Cq : (which == 1) ? Ck : Cv;
        tgemm_body<EPI_NONE, false>(A, Bm, C, SB, ND, D_, nullptr, nullptr,
                                    (t >> 3) * 128, (t & 7) * 128);
    }
}

// ---------------- ef[i,b,n,s] = (q + r_s_bias) . seg_embed[s] ----------------
__global__ void ef_kernel(const float* __restrict__ q, const float* __restrict__ rs,
                          const float* __restrict__ se, float* __restrict__ ef)
{
    int w = blockIdx.x * 4 + (threadIdx.x >> 5);   // over SB*NH
    int lane = threadIdx.x & 31;
    int row = w / NH, n = w % NH;
    int d0 = lane * 2;
    const float* qp = q + (size_t)row * ND + n * DH;
    float q0 = qp[d0]     + rs[n * DH + d0];
    float q1 = qp[d0 + 1] + rs[n * DH + d0 + 1];
    float s0 = q0 * se[(0 * NH + n) * DH + d0] + q1 * se[(0 * NH + n) * DH + d0 + 1];
    float s1 = q0 * se[(1 * NH + n) * DH + d0] + q1 * se[(1 * NH + n) * DH + d0 + 1];
    #pragma unroll
    for (int off = 16; off; off >>= 1) {
        s0 += __shfl_xor_sync(0xffffffffu, s0, off);
        s1 += __shfl_xor_sync(0xffffffffu, s1, off);
    }
    if (lane == 0) { ef[w * 2] = s0; ef[w * 2 + 1] = s1; }
}

// ---------------- fused flash attention: score + online softmax + P@V ----------------
// CTA = (head, i-tile of 64 rows). 16 warps: rg = wid&3 (row group of 16),
// sub = wid>>2 (owns score cols sub*16..+15 == its P@V k16 chunk).
// Krs kept in a 128-col ring: kr row m lives at phys col 64 + (m & 127).
struct FlashSmem {
    unsigned QA[4][32][72];                 // Qw hi/lo, Qr hi/lo [kpair][row]
    union {
        unsigned KB[2][32][200];            // hi/lo [kpair][col: 0..63 K, 64..191 Krs ring]
        float    ored[64][68];              // final O reduction
    } kb;
    float dloc[64][132];                    // Dloc table (logical u = lj-li+64)
    unsigned VB[2][32][72];                 // V hi/lo [kpair(j)][d]
    float ef_s[64][2];
    float redmax[64][4];
    float redl[64][4];
};

__global__ void __launch_bounds__(512, 1) flash_attn(
    const float* __restrict__ q, const float* __restrict__ k, const float* __restrict__ kr,
    const float* __restrict__ v,
    const float* __restrict__ rw, const float* __restrict__ rr,
    const float* __restrict__ ef, const float* __restrict__ seg_mat,
    float* __restrict__ vec)
{
    extern __shared__ char smraw[];
    FlashSmem* sm = (FlashSmem*)smraw;
    const int head = blockIdx.x;
    const int b = head / NH, n = head % NH;
    const int i0 = (15 - blockIdx.y) * 64;      // longest-running CTAs first
    const int tid = threadIdx.x;
    const int wid = tid >> 5, lane = tid & 31;
    const int g = lane >> 2, tg = lane & 3;
    const int rg = wid & 3, sub = wid >> 2;
    const int rbase = rg * 16;

    // --- load Q once (Qw = q+rw, Qr = q+rr), split to bf16 hi/lo ---
    #pragma unroll
    for (int t = 0; t < 2; t++) {
        int job = tid + t * 512;
        int li = job >> 4, kq = (job & 15) * 4;
        const float* qp = q + ((size_t)((i0 + li) * B_ + b)) * ND + n * DH + kq;
        float4 qv = *(const float4*)qp;
        float4 wv = *(const float4*)(rw + n * DH + kq);
        float4 rv = *(const float4*)(rr + n * DH + kq);
        unsigned hi, lo; int kp = kq >> 1;
        split2(qv.x + wv.x, qv.y + wv.y, hi, lo); sm->QA[0][kp][li] = hi; sm->QA[1][kp][li] = lo;
        split2(qv.z + wv.z, qv.w + wv.w, hi, lo); sm->QA[0][kp+1][li] = hi; sm->QA[1][kp+1][li] = lo;
        split2(qv.x + rv.x, qv.y + rv.y, hi, lo); sm->QA[2][kp][li] = hi; sm->QA[3][kp][li] = lo;
        split2(qv.z + rv.z, qv.w + rv.w, hi, lo); sm->QA[2][kp+1][li] = hi; sm->QA[3][kp+1][li] = lo;
    }
    if (tid < 128)
        sm->ef_s[tid >> 1][tid & 1] =
            ef[((size_t)((i0 + (tid >> 1)) * B_ + b) * NH + n) * 2 + (tid & 1)];

    float m_r[2] = {-1e30f, -1e30f};
    float l_r[2] = {0.f, 0.f};
    float accO[8][4];
    #pragma unroll
    for (int f = 0; f < 8; f++)
        #pragma unroll
        for (int r = 0; r < 4; r++) accO[f][r] = 0.f;

    // loader index precompute
    const int lK_li = tid >> 4, lK_dq = (tid & 15) * 4;   // K/Krs loaders
    const int lV_jp = tid >> 4, lV_dq = (tid & 15) * 4;   // V loader

    for (int j0 = 0; j0 <= i0; j0 += 64) {
        const int w = S_ + j0 - i0 - 64;        // ring window start (mult of 64)
        const int ofs = w & 127;
        const bool first = (j0 == 0);
        __syncthreads();   // previous iteration consumers done

        // ===== issue ALL gmem loads first =====
        float4 kv0 = *(const float4*)(k + ((size_t)((j0 + lK_li) * B_ + b)) * ND + n * DH + lK_dq);
        float4 kv1 = *(const float4*)(k + ((size_t)((j0 + lK_li + 32) * B_ + b)) * ND + n * DH + lK_dq);
        const float* vp0 = v + ((size_t)((j0 + 2 * lV_jp) * B_ + b)) * ND + n * DH + lV_dq;
        float4 vv0 = *(const float4*)vp0;
        float4 vv1 = *(const float4*)(vp0 + (size_t)B_ * ND);
        const int mstart = first ? w : (w + 64);
        float4 rv0 = *(const float4*)(kr + ((size_t)((mstart + lK_li) * B_ + b)) * ND + n * DH + lK_dq);
        float4 rv1 = *(const float4*)(kr + ((size_t)((mstart + lK_li + 32) * B_ + b)) * ND + n * DH + lK_dq);
        float4 rv2, rv3;
        if (first) {
            rv2 = *(const float4*)(kr + ((size_t)((mstart + lK_li + 64) * B_ + b)) * ND + n * DH + lK_dq);
            rv3 = *(const float4*)(kr + ((size_t)((mstart + lK_li + 96) * B_ + b)) * ND + n * DH + lK_dq);
        }
        // seg_mat prefetch for this warp's 8 score elems
        float segv[2][4];
        #pragma unroll
        for (int fa = 0; fa < 2; fa++)
            #pragma unroll
            for (int r = 0; r < 4; r++) {
                int gi = i0 + rbase + g + (r >> 1) * 8;
                int gj = j0 + sub * 16 + fa * 8 + tg * 2 + (r & 1);
                segv[fa][r] = __ldg(&seg_mat[(((size_t)gi * S_ + gj) * B_ + b) * 2 + 1]);
            }

        // ===== split + store =====
        {
            unsigned hi, lo; int kp = lK_dq >> 1;
            split2(kv0.x, kv0.y, hi, lo); sm->kb.KB[0][kp][lK_li] = hi; sm->kb.KB[1][kp][lK_li] = lo;
            split2(kv0.z, kv0.w, hi, lo); sm->kb.KB[0][kp+1][lK_li] = hi; sm->kb.KB[1][kp+1][lK_li] = lo;
            split2(kv1.x, kv1.y, hi, lo); sm->kb.KB[0][kp][lK_li + 32] = hi; sm->kb.KB[1][kp][lK_li + 32] = lo;
            split2(kv1.z, kv1.w, hi, lo); sm->kb.KB[0][kp+1][lK_li + 32] = hi; sm->kb.KB[1][kp+1][lK_li + 32] = lo;
            int c0 = 64 + ((mstart + lK_li) & 127);
            int c1 = 64 + ((mstart + lK_li + 32) & 127);
            split2(rv0.x, rv0.y, hi, lo); sm->kb.KB[0][kp][c0] = hi; sm->kb.KB[1][kp][c0] = lo;
            split2(rv0.z, rv0.w, hi, lo); sm->kb.KB[0][kp+1][c0] = hi; sm->kb.KB[1][kp+1][c0] = lo;
            split2(rv1.x, rv1.y, hi, lo); sm->kb.KB[0][kp][c1] = hi; sm->kb.KB[1][kp][c1] = lo;
            split2(rv1.z, rv1.w, hi, lo); sm->kb.KB[0][kp+1][c1] = hi; sm->kb.KB[1][kp+1][c1] = lo;
            if (first) {
                int c2 = 64 + ((mstart + lK_li + 64) & 127);
                int c3 = 64 + ((mstart + lK_li + 96) & 127);
                split2(rv2.x, rv2.y, hi, lo); sm->kb.KB[0][kp][c2] = hi; sm->kb.KB[1][kp][c2] = lo;
                split2(rv2.z, rv2.w, hi, lo); sm->kb.KB[0][kp+1][c2] = hi; sm->kb.KB[1][kp+1][c2] = lo;
                split2(rv3.x, rv3.y, hi, lo); sm->kb.KB[0][kp][c3] = hi; sm->kb.KB[1][kp][c3] = lo;
                split2(rv3.z, rv3.w, hi, lo); sm->kb.KB[0][kp+1][c3] = hi; sm->kb.KB[1][kp+1][c3] = lo;
            }
            split2(vv0.x, vv1.x, hi, lo); sm->VB[0][lV_jp][lV_dq]     = hi; sm->VB[1][lV_jp][lV_dq]     = lo;
            split2(vv0.y, vv1.y, hi, lo); sm->VB[0][lV_jp][lV_dq + 1] = hi; sm->VB[1][lV_jp][lV_dq + 1] = lo;
            split2(vv0.z, vv1.z, hi, lo); sm->VB[0][lV_jp][lV_dq + 2] = hi; sm->VB[1][lV_jp][lV_dq + 2] = lo;
            split2(vv0.w, vv1.w, hi, lo); sm->VB[0][lV_jp][lV_dq + 3] = hi; sm->VB[1][lV_jp][lV_dq + 3] = lo;
        }
        __syncthreads();

        // --- score MMAs: ac (2 frags) + Dloc (4 frags) ---
        float aS[2][4], dS[4][4];
        #pragma unroll
        for (int f = 0; f < 2; f++)
            #pragma unroll
            for (int r = 0; r < 4; r++) aS[f][r] = 0.f;
        #pragma unroll
        for (int f = 0; f < 4; f++)
            #pragma unroll
            for (int r = 0; r < 4; r++) dS[f][r] = 0.f;

        #pragma unroll
        for (int kf = 0; kf < 4; kf++) {
            int kp = kf * 8;
            unsigned wh0 = sm->QA[0][kp + tg][rbase + g],     wh1 = sm->QA[0][kp + tg][rbase + g + 8];
            unsigned wh2 = sm->QA[0][kp + tg + 4][rbase + g], wh3 = sm->QA[0][kp + tg + 4][rbase + g + 8];
            unsigned wl0 = sm->QA[1][kp + tg][rbase + g],     wl1 = sm->QA[1][kp + tg][rbase + g + 8];
            unsigned wl2 = sm->QA[1][kp + tg + 4][rbase + g], wl3 = sm->QA[1][kp + tg + 4][rbase + g + 8];
            #pragma unroll
            for (int fa = 0; fa < 2; fa++) {
                int c = (sub * 2 + fa) * 8 + g;
                unsigned bh0 = sm->kb.KB[0][kp + tg][c], bh1 = sm->kb.KB[0][kp + tg + 4][c];
                unsigned bl0 = sm->kb.KB[1][kp + tg][c], bl1 = sm->kb.KB[1][kp + tg + 4][c];
                mma_bf16(aS[fa], wh0, wh1, wh2, wh3, bh0, bh1);
                mma_bf16(aS[fa], wh0, wh1, wh2, wh3, bl0, bl1);
                mma_bf16(aS[fa], wl0, wl1, wl2, wl3, bh0, bh1);
            }
            unsigned rh0 = sm->QA[2][kp + tg][rbase + g],     rh1 = sm->QA[2][kp + tg][rbase + g + 8];
            unsigned rh2 = sm->QA[2][kp + tg + 4][rbase + g], rh3 = sm->QA[2][kp + tg + 4][rbase + g + 8];
            unsigned rl0 = sm->QA[3][kp + tg][rbase + g],     rl1 = sm->QA[3][kp + tg][rbase + g + 8];
            unsigned rl2 = sm->QA[3][kp + tg + 4][rbase + g], rl3 = sm->QA[3][kp + tg + 4][rbase + g + 8];
            #pragma unroll
            for (int fd = 0; fd < 4; fd++) {
                int c = 64 + ((ofs + sub * 32 + fd * 8) & 127) + g;
                unsigned bh0 = sm->kb.KB[0][kp + tg][c], bh1 = sm->kb.KB[0][kp + tg + 4][c];
                unsigned bl0 = sm->kb.KB[1][kp + tg][c], bl1 = sm->kb.KB[1][kp + tg + 4][c];
                mma_bf16(dS[fd], rh0, rh1, rh2, rh3, bh0, bh1);
                mma_bf16(dS[fd], rh0, rh1, rh2, rh3, bl0, bl1);
                mma_bf16(dS[fd], rl0, rl1, rl2, rl3, bh0, bh1);
            }
        }
        // dump own Dloc frags (logical u index)
        #pragma unroll
        for (int fd = 0; fd < 4; fd++)
            #pragma unroll
            for (int r = 0; r < 4; r++)
                sm->dloc[rbase + g + (r >> 1) * 8][sub * 32 + fd * 8 + tg * 2 + (r & 1)] = dS[fd][r];
        __syncthreads();

        // --- combine + warp row max ---
        float s_v[2][4];
        float wmax[2] = {-3.0e38f, -3.0e38f};
        const bool diag = (j0 == i0);
        #pragma unroll
        for (int fa = 0; fa < 2; fa++)
            #pragma unroll
            for (int r = 0; r < 4; r++) {
                int li = rbase + g + (r >> 1) * 8;
                int lj = sub * 16 + fa * 8 + tg * 2 + (r & 1);
                float val;
                if (diag && lj > li) {
                    val = -1e30f;
                } else {
                    float dl = sm->dloc[li][lj - li + 64];
                    float e0 = sm->ef_s[li][0], e1 = sm->ef_s[li][1];
                    val = (aS[fa][r] + dl + e0 + segv[fa][r] * (e1 - e0)) * 0.125f;
                }
                s_v[fa][r] = val;
                wmax[r >> 1] = fmaxf(wmax[r >> 1], val);
            }
        #pragma unroll
        for (int hh = 0; hh < 2; hh++) {
            wmax[hh] = fmaxf(wmax[hh], __shfl_xor_sync(0xffffffffu, wmax[hh], 1));
            wmax[hh] = fmaxf(wmax[hh], __shfl_xor_sync(0xffffffffu, wmax[hh], 2));
        }
        if (tg == 0) {
            sm->redmax[rbase + g][sub]     = wmax[0];
            sm->redmax[rbase + g + 8][sub] = wmax[1];
        }
        __syncthreads();

        // --- online softmax update ---
        float alpha_h[2];
        #pragma unroll
        for (int hh = 0; hh < 2; hh++) {
            int li = rbase + g + hh * 8;
            float tm = fmaxf(fmaxf(sm->redmax[li][0], sm->redmax[li][1]),
                             fmaxf(sm->redmax[li][2], sm->redmax[li][3]));
            float mnew = fmaxf(m_r[hh], tm);
            alpha_h[hh] = __expf(m_r[hh] - mnew);
            m_r[hh] = mnew;
            l_r[hh] *= alpha_h[hh];
        }
        #pragma unroll
        for (int f = 0; f < 8; f++) {
            accO[f][0] *= alpha_h[0]; accO[f][1] *= alpha_h[0];
            accO[f][2] *= alpha_h[1]; accO[f][3] *= alpha_h[1];
        }
        // --- P = exp(s - m), row partial sums, pack A-frags in-register ---
        float pv[2][4];
        float psum[2] = {0.f, 0.f};
        #pragma unroll
        for (int fa = 0; fa < 2; fa++)
            #pragma unroll
            for (int r = 0; r < 4; r++) {
                float p = __expf(s_v[fa][r] - m_r[r >> 1]);
                pv[fa][r] = p;
                psum[r >> 1] += p;
            }
        #pragma unroll
        for (int hh = 0; hh < 2; hh++) {
            psum[hh] += __shfl_xor_sync(0xffffffffu, psum[hh], 1);
            psum[hh] += __shfl_xor_sync(0xffffffffu, psum[hh], 2);
            l_r[hh] += psum[hh];
        }
        unsigned ph[4], pl[4];
        split2(pv[0][0], pv[0][1], ph[0], pl[0]);
        split2(pv[0][2], pv[0][3], ph[1], pl[1]);
        split2(pv[1][0], pv[1][1], ph[2], pl[2]);
        split2(pv[1][2], pv[1][3], ph[3], pl[3]);
        // --- P @ V (this warp's k16 chunk = V rows sub*16..+15) ---
        const int kpb = sub * 8;
        #pragma unroll
        for (int f = 0; f < 8; f++) {
            int c = f * 8 + g;
            unsigned bh0 = sm->VB[0][kpb + tg][c], bh1 = sm->VB[0][kpb + tg + 4][c];
            unsigned bl0 = sm->VB[1][kpb + tg][c], bl1 = sm->VB[1][kpb + tg + 4][c];
            mma_bf16(accO[f], ph[0], ph[1], ph[2], ph[3], bh0, bh1);
            mma_bf16(accO[f], ph[0], ph[1], ph[2], ph[3], bl0, bl1);
            mma_bf16(accO[f], pl[0], pl[1], pl[2], pl[3], bh0, bh1);
        }
    }

    // --- final: reduce K-split partials deterministically, normalize, store ---
    __syncthreads();
    if (tg == 0) {
        sm->redl[rbase + g][sub]     = l_r[0];
        sm->redl[rbase + g + 8][sub] = l_r[1];
    }
    #pragma unroll
    for (int s = 0; s < 4; s++) {
        if (sub == s) {
            #pragma unroll
            for (int f = 0; f < 8; f++)
                #pragma unroll
                for (int r = 0; r < 4; r++) {
                    int row = rbase + g + (r >> 1) * 8;
                    int col = f * 8 + tg * 2 + (r & 1);
                    if (s == 0) sm->kb.ored[row][col] = accO[f][r];
                    else        sm->kb.ored[row][col] += accO[f][r];
                }
        }
        __syncthreads();
    }
    #pragma unroll
    for (int t = 0; t < 8; t++) {
        int job = tid + t * 512;
        int row = job >> 6, col = job & 63;
        float lt = sm->redl[row][0] + sm->redl[row][1] + sm->redl[row][2] + sm->redl[row][3];
        vec[((size_t)((i0 + row) * B_ + b)) * ND + n * DH + col] = sm->kb.ored[row][col] / lt;
    }
}

// ---------------- layernorm (optional fused residual add) ----------------
__global__ void ln_kernel(const float* __restrict__ x, const float* __restrict__ res,
                          const float* __restrict__ g, const float* __restrict__ b,
                          float* __restrict__ out)
{
    __shared__ float red[256];
    const int row = blockIdx.x, tid = threadIdx.x;
    const float* xr = x + (size_t)row * D_;
    float v[4];
    float s = 0.f;
    #pragma unroll
    for (int t = 0; t < 4; t++) {
        int d = tid + t * 256;
        v[t] = xr[d];
        if (res) v[t] += res[(size_t)row * D_ + d];
        s += v[t];
    }
    red[tid] = s; __syncthreads();
    for (int o = 128; o > 0; o >>= 1) { if (tid < o) red[tid] += red[tid + o]; __syncthreads(); }
    float mean = red[0] * (1.f / D_);
    __syncthreads();
    s = 0.f;
    #pragma unroll
    for (int t = 0; t < 4; t++) { float d2 = v[t] - mean; s += d2 * d2; }
    red[tid] = s; __syncthreads();
    for (int o = 128; o > 0; o >>= 1) { if (tid < o) red[tid] += red[tid + o]; __syncthreads(); }
    float inv = rsqrtf(red[0] * (1.f / D_) + 1e-12f);
    #pragma unroll
    for (int t = 0; t < 4; t++) {
        int d = tid + t * 256;
        out[(size_t)row * D_ + d] = (v[t] - mean) * inv * g[d] + b[d];
    }
}

// ---------------- host ----------------
static float* sym_addr(const void* sym) {
    void* p = nullptr;
    cudaGetSymbolAddress(&p, sym);
    return (float*)p;
}

extern "C" void kernel_launch(void* const* d_in, const int* in_sizes, int n_in,
                              void* d_out, int out_size)
{
    (void)in_sizes; (void)n_in; (void)out_size;
    const float* h         = (const float*)d_in[0];
    const float* pos_emb   = (const float*)d_in[1];
    const float* seg_mat   = (const float*)d_in[3];
    const float* Wq        = (const float*)d_in[4];
    const float* Wk        = (const float*)d_in[5];
    const float* Wv        = (const float*)d_in[6];
    const float* Wo        = (const float*)d_in[7];
    const float* Wr        = (const float*)d_in[8];
    const float* rw        = (const float*)d_in[9];
    const float* rr        = (const float*)d_in[10];
    const float* rs        = (const float*)d_in[11];
    const float* se        = (const float*)d_in[12];
    const float* ln1g      = (const float*)d_in[13];
    const float* ln1b      = (const float*)d_in[14];
    const float* w1        = (const float*)d_in[15];
    const float* b1        = (const float*)d_in[16];
    const float* w2        = (const float*)d_in[17];
    const float* b2        = (const float*)d_in[18];
    const float* ln2g      = (const float*)d_in[19];
    const float* ln2b      = (const float*)d_in[20];
    float* out = (float*)d_out;

    float* gq    = sym_addr(g_q);
    float* gk    = sym_addr(g_k);
    float* gv    = sym_addr(g_v);
    float* gkr   = sym_addr(g_kr);
    float* gef   = sym_addr(g_ef);
    float* gvec  = sym_addr(g_vec);
    float* gattn = sym_addr(g_attn);
    float* gx    = sym_addr(g_x);
    float* gf    = sym_addr(g_f);
    float* gf2   = sym_addr(g_f2);
    float* gbuf  = sym_addr(g_buf);

    const int GS = (int)sizeof(GemmSmem);
    static bool attr_set = false;
    if (!attr_set) {
        cudaFuncSetAttribute(flash_attn, cudaFuncAttributeMaxDynamicSharedMemorySize,
                             (int)sizeof(FlashSmem));
        cudaFuncSetAttribute(proj_all, cudaFuncAttributeMaxDynamicSharedMemorySize, GS);
        cudaFuncSetAttribute(tgemm<EPI_RES, true>, cudaFuncAttributeMaxDynamicSharedMemorySize, GS);
        cudaFuncSetAttribute(tgemm<EPI_BIAS_GELU, false>, cudaFuncAttributeMaxDynamicSharedMemorySize, GS);
        cudaFuncSetAttribute(tgemm<EPI_BIAS, false>, cudaFuncAttributeMaxDynamicSharedMemorySize, GS);
        attr_set = true;
    }

    for (int l = 0; l < 2; l++) {
        const float* cur = (l == 0) ? h : gbuf;
        float* nxt = (l == 0) ? gbuf : out;
        const size_t woff = (size_t)l * D_ * ND;

        proj_all<<<144 + 384, 256, GS>>>(
            cur, pos_emb, Wq + woff, Wk + woff, Wv + woff, Wr + woff,
            gq, gk, gv, gkr);

        ef_kernel<<<SB * NH / 4, 128>>>(gq, rs + l * NH * DH, se + l * 2 * NH * DH, gef);

        flash_attn<<<dim3(NHEADS, S_ / 64), 512, sizeof(FlashSmem)>>>(
            gq, gk, gkr, gv, rw + l * NH * DH, rr + l * NH * DH,
            gef, seg_mat, gvec);

        tgemm<EPI_RES, true><<<dim3(D_ / 128, SB / 128), 256, GS>>>(
            gvec, Wo + woff, gattn, SB, D_, ND, nullptr, cur);

        ln_kernel<<<SB, 256>>>(gattn, nullptr, ln1g + l * D_, ln1b + l * D_, gx);

        tgemm<EPI_BIAS_GELU, false><<<dim3(DI_ / 128, SB / 128), 256, GS>>>(
            gx, w1 + (size_t)l * D_ * DI_, gf, SB, DI_, D_, b1 + l * DI_, nullptr);

        tgemm<EPI_BIAS, false><<<dim3(D_ / 128, SB / 128), 256, GS>>>(
            gf, w2 + (size_t)l * DI_ * D_, gf2, SB, D_, DI_, b2 + l * D_, nullptr);

        ln_kernel<<<SB, 256>>>(gf2, gx, ln2g + l * D_, ln2b + l * D_, nxt);
    }
}

// round 13
// speedup vs baseline: 1.0610x; 1.0037x over previous
#include <cuda_runtime.h>
#include <math.h>

#define S_   1024
#define B_   2
#define D_   1024
#define NH   16
#define DH   64
#define DI_  4096
#define R_   2048
#define SB   (S_*B_)          // 2048
#define RB   (R_*B_)          // 4096
#define ND   (NH*DH)          // 1024
#define NHEADS (B_*NH)        // 32
#define KRR  1152             // kr rows actually consumed (max index 1087)

// ---------------- scratch (device globals; no allocation allowed) ----------------
__device__ float g_q   [SB*ND];
__device__ float g_k   [SB*ND];
__device__ float g_v   [SB*ND];
__device__ float g_kr  [RB*ND];
__device__ float g_ef  [SB*NH*2];
__device__ float g_vec [SB*ND];
__device__ float g_attn[SB*ND];
__device__ float g_x   [SB*ND];
__device__ float g_f   [SB*DI_];
__device__ float g_f2  [SB*ND];
__device__ float g_buf [SB*ND];

enum { EPI_NONE = 0, EPI_BIAS = 1, EPI_BIAS_GELU = 2, EPI_RES = 3 };

__device__ __forceinline__ float gelu_f(float x) {
    return 0.5f * x * (1.0f + erff(x * 0.7071067811865476f));
}

// ---------------- bf16 split helpers ----------------
__device__ __forceinline__ void split2(float x0, float x1, unsigned& hi, unsigned& lo) {
    unsigned h;
    asm("cvt.rn.bf16x2.f32 %0, %1, %2;" : "=r"(h) : "f"(x1), "f"(x0));
    float h0 = __uint_as_float(h << 16);
    float h1 = __uint_as_float(h & 0xffff0000u);
    float r0 = x0 - h0;
    float r1 = x1 - h1;
    unsigned l;
    asm("cvt.rn.bf16x2.f32 %0, %1, %2;" : "=r"(l) : "f"(r1), "f"(r0));
    hi = h; lo = l;
}

__device__ __forceinline__ void mma_bf16(float* c,
    unsigned a0, unsigned a1, unsigned a2, unsigned a3, unsigned b0, unsigned b1) {
    asm volatile(
        "mma.sync.aligned.m16n8k16.row.col.f32.bf16.bf16.f32 "
        "{%0,%1,%2,%3}, {%4,%5,%6,%7}, {%8,%9}, {%0,%1,%2,%3};\n"
        : "+f"(c[0]), "+f"(c[1]), "+f"(c[2]), "+f"(c[3])
        : "r"(a0), "r"(a1), "r"(a2), "r"(a3), "r"(b0), "r"(b1));
}

// ---------------- cp.async helpers ----------------
__device__ __forceinline__ void cp16(void* smem, const void* g) {
    unsigned s = (unsigned)__cvta_generic_to_shared(smem);
    asm volatile("cp.async.cg.shared.global [%0], [%1], 16;" :: "r"(s), "l"(g));
}
__device__ __forceinline__ void cp_commit() {
    asm volatile("cp.async.commit_group;");
}
template<int N>
__device__ __forceinline__ void cp_wait() {
    asm volatile("cp.async.wait_group %0;" :: "n"(N));
}

// ---------------- GEMM shared memory (dynamic) ----------------
struct GemmSmem {
    float fA[2][128][16];        // fp32 staging for A (granule-swizzled)
    float fB[2][16 * 128];       // fp32 staging for B (NN: [k][n]; TB: [n][16] swizzled)
    unsigned Ah[2][8][136], Al[2][8][136];   // bf16 hi/lo, DOUBLE-buffered
    unsigned Bh[2][8][136], Bl[2][8][136];
};

// ---------------- tensor-core 128x128 GEMM body, bf16 split, cp.async + dual double-buffer ----------------
template<int EPI, bool TB>
__device__ __forceinline__ void tgemm_body(
    const float* __restrict__ A, const float* __restrict__ Bm, float* __restrict__ C,
    int M, int Nn, int K, const float* __restrict__ bias, const float* __restrict__ res,
    int m0, int n0)
{
    extern __shared__ char gsm_raw[];
    GemmSmem* sm = (GemmSmem*)gsm_raw;
    const int tid = threadIdx.x;
    const int wid = tid >> 5, lane = tid & 31;
    const int wm = (wid >> 2) * 64;
    const int wn = (wid & 3) * 32;
    const int g  = lane >> 2;
    const int tg = lane & 3;

    const int lm = tid >> 1, lq = (tid & 1) * 8;
    const int gq = lq >> 2;                 // 0 or 2
    const int bsw = (lm >> 1) & 1;          // granule swizzle bit
    const int pg0 = ((gq + bsw) & 3) * 4;
    const int pg1 = ((gq + 1 + bsw) & 3) * 4;
    const int bk = tid >> 5, bn = (tid & 31) * 4;

    float acc[4][4][4];
    #pragma unroll
    for (int mt = 0; mt < 4; mt++)
        #pragma unroll
        for (int nt = 0; nt < 4; nt++)
            #pragma unroll
            for (int r = 0; r < 4; r++) acc[mt][nt][r] = 0.f;

    auto cp_slab = [&](int k0, int st) {
        const float* gA = A + (size_t)(m0 + lm) * K + k0 + lq;
        float* sA = &sm->fA[st][lm][0];
        cp16(sA + pg0, gA);
        cp16(sA + pg1, gA + 4);
        if (TB) {
            const float* gB = Bm + (size_t)(n0 + lm) * K + k0 + lq;
            float* sB = &sm->fB[st][lm * 16];
            cp16(sB + pg0, gB);
            cp16(sB + pg1, gB + 4);
        } else {
            cp16(&sm->fB[st][(2 * bk) * 128 + bn],
                 Bm + (size_t)(k0 + 2 * bk) * Nn + n0 + bn);
            cp16(&sm->fB[st][(2 * bk + 1) * 128 + bn],
                 Bm + (size_t)(k0 + 2 * bk + 1) * Nn + n0 + bn);
        }
    };

    auto split_slab = [&](int st) {   // fp32 stage st -> bf16 stage st
        float a[8];
        const float* sA = &sm->fA[st][lm][0];
        *(float4*)(a)     = *(const float4*)(sA + pg0);
        *(float4*)(a + 4) = *(const float4*)(sA + pg1);
        #pragma unroll
        for (int j = 0; j < 4; j++) {
            unsigned hi, lo;
            split2(a[2 * j], a[2 * j + 1], hi, lo);
            sm->Ah[st][(lq >> 1) + j][lm] = hi;
            sm->Al[st][(lq >> 1) + j][lm] = lo;
        }
        if (TB) {
            float b[8];
            const float* sB = &sm->fB[st][lm * 16];
            *(float4*)(b)     = *(const float4*)(sB + pg0);
            *(float4*)(b + 4) = *(const float4*)(sB + pg1);
            #pragma unroll
            for (int j = 0; j < 4; j++) {
                unsigned hi, lo;
                split2(b[2 * j], b[2 * j + 1], hi, lo);
                sm->Bh[st][(lq >> 1) + j][lm] = hi;
                sm->Bl[st][(lq >> 1) + j][lm] = lo;
            }
        } else {
            float b[8];
            *(float4*)(b)     = *(const float4*)&sm->fB[st][(2 * bk) * 128 + bn];
            *(float4*)(b + 4) = *(const float4*)&sm->fB[st][(2 * bk + 1) * 128 + bn];
            #pragma unroll
            for (int j = 0; j < 4; j++) {
                unsigned hi, lo;
                split2(b[j], b[4 + j], hi, lo);
                sm->Bh[st][bk][bn + j] = hi;
                sm->Bl[st][bk][bn + j] = lo;
            }
        }
    };

    auto compute = [&](int st) {
        unsigned bh0[4], bh1[4], bl0[4], bl1[4];
        #pragma unroll
        for (int nt = 0; nt < 4; nt++) {
            int c = wn + nt * 8 + g;
            bh0[nt] = sm->Bh[st][tg][c];     bh1[nt] = sm->Bh[st][tg + 4][c];
            bl0[nt] = sm->Bl[st][tg][c];     bl1[nt] = sm->Bl[st][tg + 4][c];
        }
        #pragma unroll
        for (int mt = 0; mt < 4; mt++) {
            int r0c = wm + mt * 16 + g;
            unsigned ah0 = sm->Ah[st][tg][r0c],     ah1 = sm->Ah[st][tg][r0c + 8];
            unsigned ah2 = sm->Ah[st][tg + 4][r0c], ah3 = sm->Ah[st][tg + 4][r0c + 8];
            unsigned al0 = sm->Al[st][tg][r0c],     al1 = sm->Al[st][tg][r0c + 8];
            unsigned al2 = sm->Al[st][tg + 4][r0c], al3 = sm->Al[st][tg + 4][r0c + 8];
            #pragma unroll
            for (int nt = 0; nt < 4; nt++) {
                float* c = acc[mt][nt];
                mma_bf16(c, ah0, ah1, ah2, ah3, bh0[nt], bh1[nt]);
                mma_bf16(c, ah0, ah1, ah2, ah3, bl0[nt], bl1[nt]);
                mma_bf16(c, al0, al1, al2, al3, bh0[nt], bh1[nt]);
            }
        }
    };

    const int nslab = K >> 4;   // >= 2 always here
    cp_slab(0, 0);  cp_commit();
    cp_slab(16, 1); cp_commit();
    cp_wait<1>();               // slab 0 landed
    split_slab(0);
    __syncthreads();

    for (int kt = 0; kt < nslab; kt++) {
        const int st = kt & 1;
        if (kt + 2 < nslab) { cp_slab((kt + 2) << 4, st); cp_commit(); }
        compute(st);            // reads bf16 stage st
        if (kt + 1 < nslab) {
            if (kt + 2 < nslab) cp_wait<1>(); else cp_wait<0>();
            split_slab(st ^ 1); // writes bf16 stage st^1 (disjoint from compute's reads)
        }
        __syncthreads();
    }

    #pragma unroll
    for (int mt = 0; mt < 4; mt++) {
        int r0 = m0 + wm + mt * 16 + g;
        #pragma unroll
        for (int nt = 0; nt < 4; nt++) {
            int c0 = n0 + wn + nt * 8 + tg * 2;
            #pragma unroll
            for (int r = 0; r < 4; r++) {
                int mm = r0 + (r >> 1) * 8;
                int nn = c0 + (r & 1);
                float v = acc[mt][nt][r];
                if (EPI == EPI_BIAS || EPI == EPI_BIAS_GELU) v += bias[nn];
                if (EPI == EPI_BIAS_GELU) v = gelu_f(v);
                if (EPI == EPI_RES) v += res[(size_t)mm * Nn + nn];
                C[(size_t)mm * Nn + nn] = v;
            }
        }
    }
}

template<int EPI, bool TB>
__global__ void __launch_bounds__(256, 2) tgemm(
    const float* __restrict__ A, const float* __restrict__ Bm, float* __restrict__ C,
    int M, int Nn, int K, const float* __restrict__ bias, const float* __restrict__ res)
{
    tgemm_body<EPI, TB>(A, Bm, C, M, Nn, K, bias, res, blockIdx.y * 128, blockIdx.x * 128);
}

// merged projections: Wr (blocks 0..143), then Q,K,V (blocks 144..527)
__global__ void __launch_bounds__(256, 2) proj_all(
    const float* __restrict__ A, const float* __restrict__ pos_emb,
    const float* __restrict__ Wq, const float* __restrict__ Wk,
    const float* __restrict__ Wv, const float* __restrict__ Wr,
    float* __restrict__ Cq, float* __restrict__ Ck, float* __restrict__ Cv,
    float* __restrict__ Ckr)
{
    int idx = blockIdx.x;
    if (idx < 144) {
        tgemm_body<EPI_NONE, false>(pos_emb, Wr, Ckr, KRR * B_, ND, D_, nullptr, nullptr,
                                    (idx >> 3) * 128, (idx & 7) * 128);
    } else {
        idx -= 144;
        int which = idx >> 7;     // 0..2
        int t = idx & 127;
        const float* Bm = (which == 0) ? Wq : (which == 1) ? Wk : Wv;
        float* C        = (which == 0) ? Cq : (which == 1) ? Ck : Cv;
        tgemm_body<EPI_NONE, false>(A, Bm, C, SB, ND, D_, nullptr, nullptr,
                                    (t >> 3) * 128, (t & 7) * 128);
    }
}

// ---------------- ef[i,b,n,s] = (q + r_s_bias) . seg_embed[s] ----------------
__global__ void ef_kernel(const float* __restrict__ q, const float* __restrict__ rs,
                          const float* __restrict__ se, float* __restrict__ ef)
{
    int w = blockIdx.x * 4 + (threadIdx.x >> 5);   // over SB*NH
    int lane = threadIdx.x & 31;
    int row = w / NH, n = w % NH;
    int d0 = lane * 2;
    const float* qp = q + (size_t)row * ND + n * DH;
    float q0 = qp[d0]     + rs[n * DH + d0];
    float q1 = qp[d0 + 1] + rs[n * DH + d0 + 1];
    float s0 = q0 * se[(0 * NH + n) * DH + d0] + q1 * se[(0 * NH + n) * DH + d0 + 1];
    float s1 = q0 * se[(1 * NH + n) * DH + d0] + q1 * se[(1 * NH + n) * DH + d0 + 1];
    #pragma unroll
    for (int off = 16; off; off >>= 1) {
        s0 += __shfl_xor_sync(0xffffffffu, s0, off);
        s1 += __shfl_xor_sync(0xffffffffu, s1, off);
    }
    if (lane == 0) { ef[w * 2] = s0; ef[w * 2 + 1] = s1; }
}

// ---------------- fused flash attention: score + online softmax + P@V ----------------
// CTA = (head, i-tile of 64 rows). 16 warps: rg = wid&3 (row group of 16),
// sub = wid>>2 (owns score cols sub*16..+15 == its P@V k16 chunk).
// Krs kept in a 128-col ring: kr row m lives at phys col 64 + (m & 127).
struct FlashSmem {
    unsigned QA[4][32][72];                 // Qw hi/lo, Qr hi/lo [kpair][row]
    union {
        unsigned KB[2][32][200];            // hi/lo [kpair][col: 0..63 K, 64..191 Krs ring]
        float    ored[64][68];              // final O reduction
    } kb;
    float dloc[64][132];                    // Dloc table (logical u = lj-li+64)
    unsigned VB[2][32][72];                 // V hi/lo [kpair(j)][d]
    float ef_s[64][2];
    float redmax[64][4];
    float redl[64][4];
};

__global__ void __launch_bounds__(512, 1) flash_attn(
    const float* __restrict__ q, const float* __restrict__ k, const float* __restrict__ kr,
    const float* __restrict__ v,
    const float* __restrict__ rw, const float* __restrict__ rr,
    const float* __restrict__ ef, const float* __restrict__ seg_mat,
    float* __restrict__ vec)
{
    extern __shared__ char smraw[];
    FlashSmem* sm = (FlashSmem*)smraw;
    const int head = blockIdx.x;
    const int b = head / NH, n = head % NH;
    const int i0 = (15 - blockIdx.y) * 64;      // longest-running CTAs first
    const int tid = threadIdx.x;
    const int wid = tid >> 5, lane = tid & 31;
    const int g = lane >> 2, tg = lane & 3;
    const int rg = wid & 3, sub = wid >> 2;
    const int rbase = rg * 16;

    // --- load Q once (Qw = q+rw, Qr = q+rr), split to bf16 hi/lo ---
    #pragma unroll
    for (int t = 0; t < 2; t++) {
        int job = tid + t * 512;
        int li = job >> 4, kq = (job & 15) * 4;
        const float* qp = q + ((size_t)((i0 + li) * B_ + b)) * ND + n * DH + kq;
        float4 qv = *(const float4*)qp;
        float4 wv = *(const float4*)(rw + n * DH + kq);
        float4 rv = *(const float4*)(rr + n * DH + kq);
        unsigned hi, lo; int kp = kq >> 1;
        split2(qv.x + wv.x, qv.y + wv.y, hi, lo); sm->QA[0][kp][li] = hi; sm->QA[1][kp][li] = lo;
        split2(qv.z + wv.z, qv.w + wv.w, hi, lo); sm->QA[0][kp+1][li] = hi; sm->QA[1][kp+1][li] = lo;
        split2(qv.x + rv.x, qv.y + rv.y, hi, lo); sm->QA[2][kp][li] = hi; sm->QA[3][kp][li] = lo;
        split2(qv.z + rv.z, qv.w + rv.w, hi, lo); sm->QA[2][kp+1][li] = hi; sm->QA[3][kp+1][li] = lo;
    }
    if (tid < 128)
        sm->ef_s[tid >> 1][tid & 1] =
            ef[((size_t)((i0 + (tid >> 1)) * B_ + b) * NH + n) * 2 + (tid & 1)];

    float m_r[2] = {-1e30f, -1e30f};
    float l_r[2] = {0.f, 0.f};
    float accO[8][4];
    #pragma unroll
    for (int f = 0; f < 8; f++)
        #pragma unroll
        for (int r = 0; r < 4; r++) accO[f][r] = 0.f;

    // loader index precompute
    const int lK_li = tid >> 4, lK_dq = (tid & 15) * 4;   // K/Krs loaders
    const int lV_jp = tid >> 4, lV_dq = (tid & 15) * 4;   // V loader

    for (int j0 = 0; j0 <= i0; j0 += 64) {
        const int w = S_ + j0 - i0 - 64;        // ring window start (mult of 64)
        const int ofs = w & 127;
        const bool first = (j0 == 0);
        __syncthreads();   // previous iteration consumers done

        // ===== issue ALL gmem loads first =====
        float4 kv0 = *(const float4*)(k + ((size_t)((j0 + lK_li) * B_ + b)) * ND + n * DH + lK_dq);
        float4 kv1 = *(const float4*)(k + ((size_t)((j0 + lK_li + 32) * B_ + b)) * ND + n * DH + lK_dq);
        const float* vp0 = v + ((size_t)((j0 + 2 * lV_jp) * B_ + b)) * ND + n * DH + lV_dq;
        float4 vv0 = *(const float4*)vp0;
        float4 vv1 = *(const float4*)(vp0 + (size_t)B_ * ND);
        const int mstart = first ? w : (w + 64);
        float4 rv0 = *(const float4*)(kr + ((size_t)((mstart + lK_li) * B_ + b)) * ND + n * DH + lK_dq);
        float4 rv1 = *(const float4*)(kr + ((size_t)((mstart + lK_li + 32) * B_ + b)) * ND + n * DH + lK_dq);
        float4 rv2, rv3;
        if (first) {
            rv2 = *(const float4*)(kr + ((size_t)((mstart + lK_li + 64) * B_ + b)) * ND + n * DH + lK_dq);
            rv3 = *(const float4*)(kr + ((size_t)((mstart + lK_li + 96) * B_ + b)) * ND + n * DH + lK_dq);
        }
        // seg_mat prefetch for this warp's 8 score elems
        float segv[2][4];
        #pragma unroll
        for (int fa = 0; fa < 2; fa++)
            #pragma unroll
            for (int r = 0; r < 4; r++) {
                int gi = i0 + rbase + g + (r >> 1) * 8;
                int gj = j0 + sub * 16 + fa * 8 + tg * 2 + (r & 1);
                segv[fa][r] = __ldg(&seg_mat[(((size_t)gi * S_ + gj) * B_ + b) * 2 + 1]);
            }

        // ===== split + store =====
        {
            unsigned hi, lo; int kp = lK_dq >> 1;
            split2(kv0.x, kv0.y, hi, lo); sm->kb.KB[0][kp][lK_li] = hi; sm->kb.KB[1][kp][lK_li] = lo;
            split2(kv0.z, kv0.w, hi, lo); sm->kb.KB[0][kp+1][lK_li] = hi; sm->kb.KB[1][kp+1][lK_li] = lo;
            split2(kv1.x, kv1.y, hi, lo); sm->kb.KB[0][kp][lK_li + 32] = hi; sm->kb.KB[1][kp][lK_li + 32] = lo;
            split2(kv1.z, kv1.w, hi, lo); sm->kb.KB[0][kp+1][lK_li + 32] = hi; sm->kb.KB[1][kp+1][lK_li + 32] = lo;
            int c0 = 64 + ((mstart + lK_li) & 127);
            int c1 = 64 + ((mstart + lK_li + 32) & 127);
            split2(rv0.x, rv0.y, hi, lo); sm->kb.KB[0][kp][c0] = hi; sm->kb.KB[1][kp][c0] = lo;
            split2(rv0.z, rv0.w, hi, lo); sm->kb.KB[0][kp+1][c0] = hi; sm->kb.KB[1][kp+1][c0] = lo;
            split2(rv1.x, rv1.y, hi, lo); sm->kb.KB[0][kp][c1] = hi; sm->kb.KB[1][kp][c1] = lo;
            split2(rv1.z, rv1.w, hi, lo); sm->kb.KB[0][kp+1][c1] = hi; sm->kb.KB[1][kp+1][c1] = lo;
            if (first) {
                int c2 = 64 + ((mstart + lK_li + 64) & 127);
                int c3 = 64 + ((mstart + lK_li + 96) & 127);
                split2(rv2.x, rv2.y, hi, lo); sm->kb.KB[0][kp][c2] = hi; sm->kb.KB[1][kp][c2] = lo;
                split2(rv2.z, rv2.w, hi, lo); sm->kb.KB[0][kp+1][c2] = hi; sm->kb.KB[1][kp+1][c2] = lo;
                split2(rv3.x, rv3.y, hi, lo); sm->kb.KB[0][kp][c3] = hi; sm->kb.KB[1][kp][c3] = lo;
                split2(rv3.z, rv3.w, hi, lo); sm->kb.KB[0][kp+1][c3] = hi; sm->kb.KB[1][kp+1][c3] = lo;
            }
            split2(vv0.x, vv1.x, hi, lo); sm->VB[0][lV_jp][lV_dq]     = hi; sm->VB[1][lV_jp][lV_dq]     = lo;
            split2(vv0.y, vv1.y, hi, lo); sm->VB[0][lV_jp][lV_dq + 1] = hi; sm->VB[1][lV_jp][lV_dq + 1] = lo;
            split2(vv0.z, vv1.z, hi, lo); sm->VB[0][lV_jp][lV_dq + 2] = hi; sm->VB[1][lV_jp][lV_dq + 2] = lo;
            split2(vv0.w, vv1.w, hi, lo); sm->VB[0][lV_jp][lV_dq + 3] = hi; sm->VB[1][lV_jp][lV_dq + 3] = lo;
        }
        __syncthreads();

        // --- score MMAs: ac (2 frags) + Dloc (4 frags) ---
        float aS[2][4], dS[4][4];
        #pragma unroll
        for (int f = 0; f < 2; f++)
            #pragma unroll
            for (int r = 0; r < 4; r++) aS[f][r] = 0.f;
        #pragma unroll
        for (int f = 0; f < 4; f++)
            #pragma unroll
            for (int r = 0; r < 4; r++) dS[f][r] = 0.f;

        #pragma unroll
        for (int kf = 0; kf < 4; kf++) {
            int kp = kf * 8;
            unsigned wh0 = sm->QA[0][kp + tg][rbase + g],     wh1 = sm->QA[0][kp + tg][rbase + g + 8];
            unsigned wh2 = sm->QA[0][kp + tg + 4][rbase + g], wh3 = sm->QA[0][kp + tg + 4][rbase + g + 8];
            unsigned wl0 = sm->QA[1][kp + tg][rbase + g],     wl1 = sm->QA[1][kp + tg][rbase + g + 8];
            unsigned wl2 = sm->QA[1][kp + tg + 4][rbase + g], wl3 = sm->QA[1][kp + tg + 4][rbase + g + 8];
            #pragma unroll
            for (int fa = 0; fa < 2; fa++) {
                int c = (sub * 2 + fa) * 8 + g;
                unsigned bh0 = sm->kb.KB[0][kp + tg][c], bh1 = sm->kb.KB[0][kp + tg + 4][c];
                unsigned bl0 = sm->kb.KB[1][kp + tg][c], bl1 = sm->kb.KB[1][kp + tg + 4][c];
                mma_bf16(aS[fa], wh0, wh1, wh2, wh3, bh0, bh1);
                mma_bf16(aS[fa], wh0, wh1, wh2, wh3, bl0, bl1);
                mma_bf16(aS[fa], wl0, wl1, wl2, wl3, bh0, bh1);
            }
            unsigned rh0 = sm->QA[2][kp + tg][rbase + g],     rh1 = sm->QA[2][kp + tg][rbase + g + 8];
            unsigned rh2 = sm->QA[2][kp + tg + 4][rbase + g], rh3 = sm->QA[2][kp + tg + 4][rbase + g + 8];
            unsigned rl0 = sm->QA[3][kp + tg][rbase + g],     rl1 = sm->QA[3][kp + tg][rbase + g + 8];
            unsigned rl2 = sm->QA[3][kp + tg + 4][rbase + g], rl3 = sm->QA[3][kp + tg + 4][rbase + g + 8];
            #pragma unroll
            for (int fd = 0; fd < 4; fd++) {
                int c = 64 + ((ofs + sub * 32 + fd * 8) & 127) + g;
                unsigned bh0 = sm->kb.KB[0][kp + tg][c], bh1 = sm->kb.KB[0][kp + tg + 4][c];
                unsigned bl0 = sm->kb.KB[1][kp + tg][c], bl1 = sm->kb.KB[1][kp + tg + 4][c];
                mma_bf16(dS[fd], rh0, rh1, rh2, rh3, bh0, bh1);
                mma_bf16(dS[fd], rh0, rh1, rh2, rh3, bl0, bl1);
                mma_bf16(dS[fd], rl0, rl1, rl2, rl3, bh0, bh1);
            }
        }
        // dump own Dloc frags (logical u index)
        #pragma unroll
        for (int fd = 0; fd < 4; fd++)
            #pragma unroll
            for (int r = 0; r < 4; r++)
                sm->dloc[rbase + g + (r >> 1) * 8][sub * 32 + fd * 8 + tg * 2 + (r & 1)] = dS[fd][r];
        __syncthreads();

        // --- combine + warp row max ---
        float s_v[2][4];
        float wmax[2] = {-3.0e38f, -3.0e38f};
        const bool diag = (j0 == i0);
        #pragma unroll
        for (int fa = 0; fa < 2; fa++)
            #pragma unroll
            for (int r = 0; r < 4; r++) {
                int li = rbase + g + (r >> 1) * 8;
                int lj = sub * 16 + fa * 8 + tg * 2 + (r & 1);
                float val;
                if (diag && lj > li) {
                    val = -1e30f;
                } else {
                    float dl = sm->dloc[li][lj - li + 64];
                    float e0 = sm->ef_s[li][0], e1 = sm->ef_s[li][1];
                    val = (aS[fa][r] + dl + e0 + segv[fa][r] * (e1 - e0)) * 0.125f;
                }
                s_v[fa][r] = val;
                wmax[r >> 1] = fmaxf(wmax[r >> 1], val);
            }
        #pragma unroll
        for (int hh = 0; hh < 2; hh++) {
            wmax[hh] = fmaxf(wmax[hh], __shfl_xor_sync(0xffffffffu, wmax[hh], 1));
            wmax[hh] = fmaxf(wmax[hh], __shfl_xor_sync(0xffffffffu, wmax[hh], 2));
        }
        if (tg == 0) {
            sm->redmax[rbase + g][sub]     = wmax[0];
            sm->redmax[rbase + g + 8][sub] = wmax[1];
        }
        __syncthreads();

        // --- online softmax update ---
        float alpha_h[2];
        #pragma unroll
        for (int hh = 0; hh < 2; hh++) {
            int li = rbase + g + hh * 8;
            float tm = fmaxf(fmaxf(sm->redmax[li][0], sm->redmax[li][1]),
                             fmaxf(sm->redmax[li][2], sm->redmax[li][3]));
            float mnew = fmaxf(m_r[hh], tm);
            alpha_h[hh] = __expf(m_r[hh] - mnew);
            m_r[hh] = mnew;
            l_r[hh] *= alpha_h[hh];
        }
        #pragma unroll
        for (int f = 0; f < 8; f++) {
            accO[f][0] *= alpha_h[0]; accO[f][1] *= alpha_h[0];
            accO[f][2] *= alpha_h[1]; accO[f][3] *= alpha_h[1];
        }
        // --- P = exp(s - m), row partial sums, pack A-frags in-register ---
        float pv[2][4];
        float psum[2] = {0.f, 0.f};
        #pragma unroll
        for (int fa = 0; fa < 2; fa++)
            #pragma unroll
            for (int r = 0; r < 4; r++) {
                float p = __expf(s_v[fa][r] - m_r[r >> 1]);
                pv[fa][r] = p;
                psum[r >> 1] += p;
            }
        #pragma unroll
        for (int hh = 0; hh < 2; hh++) {
            psum[hh] += __shfl_xor_sync(0xffffffffu, psum[hh], 1);
            psum[hh] += __shfl_xor_sync(0xffffffffu, psum[hh], 2);
            l_r[hh] += psum[hh];
        }
        unsigned ph[4], pl[4];
        split2(pv[0][0], pv[0][1], ph[0], pl[0]);
        split2(pv[0][2], pv[0][3], ph[1], pl[1]);
        split2(pv[1][0], pv[1][1], ph[2], pl[2]);
        split2(pv[1][2], pv[1][3], ph[3], pl[3]);
        // --- P @ V (this warp's k16 chunk = V rows sub*16..+15) ---
        const int kpb = sub * 8;
        #pragma unroll
        for (int f = 0; f < 8; f++) {
            int c = f * 8 + g;
            unsigned bh0 = sm->VB[0][kpb + tg][c], bh1 = sm->VB[0][kpb + tg + 4][c];
            unsigned bl0 = sm->VB[1][kpb + tg][c], bl1 = sm->VB[1][kpb + tg + 4][c];
            mma_bf16(accO[f], ph[0], ph[1], ph[2], ph[3], bh0, bh1);
            mma_bf16(accO[f], ph[0], ph[1], ph[2], ph[3], bl0, bl1);
            mma_bf16(accO[f], pl[0], pl[1], pl[2], pl[3], bh0, bh1);
        }
    }

    // --- final: reduce K-split partials deterministically, normalize, store ---
    __syncthreads();
    if (tg == 0) {
        sm->redl[rbase + g][sub]     = l_r[0];
        sm->redl[rbase + g + 8][sub] = l_r[1];
    }
    #pragma unroll
    for (int s = 0; s < 4; s++) {
        if (sub == s) {
            #pragma unroll
            for (int f = 0; f < 8; f++)
                #pragma unroll
                for (int r = 0; r < 4; r++) {
                    int row = rbase + g + (r >> 1) * 8;
                    int col = f * 8 + tg * 2 + (r & 1);
                    if (s == 0) sm->kb.ored[row][col] = accO[f][r];
                    else        sm->kb.ored[row][col] += accO[f][r];
                }
        }
        __syncthreads();
    }
    #pragma unroll
    for (int t = 0; t < 8; t++) {
        int job = tid + t * 512;
        int row = job >> 6, col = job & 63;
        float lt = sm->redl[row][0] + sm->redl[row][1] + sm->redl[row][2] + sm->redl[row][3];
        vec[((size_t)((i0 + row) * B_ + b)) * ND + n * DH + col] = sm->kb.ored[row][col] / lt;
    }
}

// ---------------- layernorm (optional fused residual add) ----------------
__global__ void ln_kernel(const float* __restrict__ x, const float* __restrict__ res,
                          const float* __restrict__ g, const float* __restrict__ b,
                          float* __restrict__ out)
{
    __shared__ float red[256];
    const int row = blockIdx.x, tid = threadIdx.x;
    const float* xr = x + (size_t)row * D_;
    float v[4];
    float s = 0.f;
    #pragma unroll
    for (int t = 0; t < 4; t++) {
        int d = tid + t * 256;
        v[t] = xr[d];
        if (res) v[t] += res[(size_t)row * D_ + d];
        s += v[t];
    }
    red[tid] = s; __syncthreads();
    for (int o = 128; o > 0; o >>= 1) { if (tid < o) red[tid] += red[tid + o]; __syncthreads(); }
    float mean = red[0] * (1.f / D_);
    __syncthreads();
    s = 0.f;
    #pragma unroll
    for (int t = 0; t < 4; t++) { float d2 = v[t] - mean; s += d2 * d2; }
    red[tid] = s; __syncthreads();
    for (int o = 128; o > 0; o >>= 1) { if (tid < o) red[tid] += red[tid + o]; __syncthreads(); }
    float inv = rsqrtf(red[0] * (1.f / D_) + 1e-12f);
    #pragma unroll
    for (int t = 0; t < 4; t++) {
        int d = tid + t * 256;
        out[(size_t)row * D_ + d] = (v[t] - mean) * inv * g[d] + b[d];
    }
}

// ---------------- host ----------------
static float* sym_addr(const void* sym) {
    void* p = nullptr;
    cudaGetSymbolAddress(&p, sym);
    return (float*)p;
}

extern "C" void kernel_launch(void* const* d_in, const int* in_sizes, int n_in,
                              void* d_out, int out_size)
{
    (void)in_sizes; (void)n_in; (void)out_size;
    const float* h         = (const float*)d_in[0];
    const float* pos_emb   = (const float*)d_in[1];
    const float* seg_mat   = (const float*)d_in[3];
    const float* Wq        = (const float*)d_in[4];
    const float* Wk        = (const float*)d_in[5];
    const float* Wv        = (const float*)d_in[6];
    const float* Wo        = (const float*)d_in[7];
    const float* Wr        = (const float*)d_in[8];
    const float* rw        = (const float*)d_in[9];
    const float* rr        = (const float*)d_in[10];
    const float* rs        = (const float*)d_in[11];
    const float* se        = (const float*)d_in[12];
    const float* ln1g      = (const float*)d_in[13];
    const float* ln1b      = (const float*)d_in[14];
    const float* w1        = (const float*)d_in[15];
    const float* b1        = (const float*)d_in[16];
    const float* w2        = (const float*)d_in[17];
    const float* b2        = (const float*)d_in[18];
    const float* ln2g      = (const float*)d_in[19];
    const float* ln2b      = (const float*)d_in[20];
    float* out = (float*)d_out;

    float* gq    = sym_addr(g_q);
    float* gk    = sym_addr(g_k);
    float* gv    = sym_addr(g_v);
    float* gkr   = sym_addr(g_kr);
    float* gef   = sym_addr(g_ef);
    float* gvec  = sym_addr(g_vec);
    float* gattn = sym_addr(g_attn);
    float* gx    = sym_addr(g_x);
    float* gf    = sym_addr(g_f);
    float* gf2   = sym_addr(g_f2);
    float* gbuf  = sym_addr(g_buf);

    const int GS = (int)sizeof(GemmSmem);
    static bool attr_set = false;
    if (!attr_set) {
        cudaFuncSetAttribute(flash_attn, cudaFuncAttributeMaxDynamicSharedMemorySize,
                             (int)sizeof(FlashSmem));
        cudaFuncSetAttribute(proj_all, cudaFuncAttributeMaxDynamicSharedMemorySize, GS);
        cudaFuncSetAttribute(tgemm<EPI_RES, true>, cudaFuncAttributeMaxDynamicSharedMemorySize, GS);
        cudaFuncSetAttribute(tgemm<EPI_BIAS_GELU, false>, cudaFuncAttributeMaxDynamicSharedMemorySize, GS);
        cudaFuncSetAttribute(tgemm<EPI_BIAS, false>, cudaFuncAttributeMaxDynamicSharedMemorySize, GS);
        attr_set = true;
    }

    for (int l = 0; l < 2; l++) {
        const float* cur = (l == 0) ? h : gbuf;
        float* nxt = (l == 0) ? gbuf : out;
        const size_t woff = (size_t)l * D_ * ND;

        proj_all<<<144 + 384, 256, GS>>>(
            cur, pos_emb, Wq + woff, Wk + woff, Wv + woff, Wr + woff,
            gq, gk, gv, gkr);

        ef_kernel<<<SB * NH / 4, 128>>>(gq, rs + l * NH * DH, se + l * 2 * NH * DH, gef);

        flash_attn<<<dim3(NHEADS, S_ / 64), 512, sizeof(FlashSmem)>>>(
            gq, gk, gkr, gv, rw + l * NH * DH, rr + l * NH * DH,
            gef, seg_mat, gvec);

        tgemm<EPI_RES, true><<<dim3(D_ / 128, SB / 128), 256, GS>>>(
            gvec, Wo + woff, gattn, SB, D_, ND, nullptr, cur);

        ln_kernel<<<SB, 256>>>(gattn, nullptr, ln1g + l * D_, ln1b + l * D_, gx);

        tgemm<EPI_BIAS_GELU, false><<<dim3(DI_ / 128, SB / 128), 256, GS>>>(
            gx, w1 + (size_t)l * D_ * DI_, gf, SB, DI_, D_, b1 + l * DI_, nullptr);

        tgemm<EPI_BIAS, false><<<dim3(D_ / 128, SB / 128), 256, GS>>>(
            gf, w2 + (size_t)l * DI_ * D_, gf2, SB, D_, DI_, b2 + l * D_, nullptr);

        ln_kernel<<<SB, 256>>>(gf2, gx, ln2g + l * D_, ln2b + l * D_, nxt);
    }
}

// round 14
// speedup vs baseline: 1.1194x; 1.0551x over previous
#include <cuda_runtime.h>
#include <math.h>

#define S_   1024
#define B_   2
#define D_   1024
#define NH   16
#define DH   64
#define DI_  4096
#define R_   2048
#define SB   (S_*B_)          // 2048
#define RB   (R_*B_)          // 4096
#define ND   (NH*DH)          // 1024
#define NHEADS (B_*NH)        // 32
#define KRR  1152             // kr rows actually consumed (max index 1087)

// ---------------- scratch (device globals; no allocation allowed) ----------------
__device__ float g_q   [SB*ND];
__device__ float g_k   [SB*ND];
__device__ float g_v   [SB*ND];
__device__ float g_kr  [RB*ND];
__device__ float g_ef  [SB*NH*2];
__device__ float g_vec [SB*ND];
__device__ float g_attn[SB*ND];
__device__ float g_p1  [SB*ND];
__device__ float g_x   [SB*ND];
__device__ float g_f   [SB*DI_];
__device__ float g_f2  [SB*ND];
__device__ float g_buf [SB*ND];

enum { EPI_NONE = 0, EPI_BIAS = 1, EPI_BIAS_GELU = 2, EPI_RES = 3 };

__device__ __forceinline__ float gelu_f(float x) {
    return 0.5f * x * (1.0f + erff(x * 0.7071067811865476f));
}

// ---------------- bf16 split helpers ----------------
__device__ __forceinline__ void split2(float x0, float x1, unsigned& hi, unsigned& lo) {
    unsigned h;
    asm("cvt.rn.bf16x2.f32 %0, %1, %2;" : "=r"(h) : "f"(x1), "f"(x0));
    float h0 = __uint_as_float(h << 16);
    float h1 = __uint_as_float(h & 0xffff0000u);
    float r0 = x0 - h0;
    float r1 = x1 - h1;
    unsigned l;
    asm("cvt.rn.bf16x2.f32 %0, %1, %2;" : "=r"(l) : "f"(r1), "f"(r0));
    hi = h; lo = l;
}

__device__ __forceinline__ void mma_bf16(float* c,
    unsigned a0, unsigned a1, unsigned a2, unsigned a3, unsigned b0, unsigned b1) {
    asm volatile(
        "mma.sync.aligned.m16n8k16.row.col.f32.bf16.bf16.f32 "
        "{%0,%1,%2,%3}, {%4,%5,%6,%7}, {%8,%9}, {%0,%1,%2,%3};\n"
        : "+f"(c[0]), "+f"(c[1]), "+f"(c[2]), "+f"(c[3])
        : "r"(a0), "r"(a1), "r"(a2), "r"(a3), "r"(b0), "r"(b1));
}

// ---------------- cp.async helpers ----------------
__device__ __forceinline__ void cp16(void* smem, const void* g) {
    unsigned s = (unsigned)__cvta_generic_to_shared(smem);
    asm volatile("cp.async.cg.shared.global [%0], [%1], 16;" :: "r"(s), "l"(g));
}
__device__ __forceinline__ void cp_commit() {
    asm volatile("cp.async.commit_group;");
}
template<int N>
__device__ __forceinline__ void cp_wait() {
    asm volatile("cp.async.wait_group %0;" :: "n"(N));
}

// ---------------- GEMM shared memory (dynamic) ----------------
struct GemmSmem {
    float fA[2][128][16];        // fp32 staging for A (granule-swizzled)
    float fB[2][16 * 128];       // fp32 staging for B (NN: [k][n]; TB: [n][16] swizzled)
    unsigned Ah[2][8][136], Al[2][8][136];   // bf16 hi/lo, double-buffered
    unsigned Bh[2][8][136], Bl[2][8][136];
};

// ---------------- tensor-core 128x128 GEMM body, bf16 split, cp.async + dual double-buffer ----------------
// K = loop extent; lda = row stride of A (and of B when TB). B (NN) must be pre-offset.
template<int EPI, bool TB>
__device__ __forceinline__ void tgemm_body(
    const float* __restrict__ A, const float* __restrict__ Bm, float* __restrict__ C,
    int M, int Nn, int K, int lda, const float* __restrict__ bias, const float* __restrict__ res,
    int m0, int n0)
{
    extern __shared__ char gsm_raw[];
    GemmSmem* sm = (GemmSmem*)gsm_raw;
    const int tid = threadIdx.x;
    const int wid = tid >> 5, lane = tid & 31;
    const int wm = (wid >> 2) * 64;
    const int wn = (wid & 3) * 32;
    const int g  = lane >> 2;
    const int tg = lane & 3;

    const int lm = tid >> 1, lq = (tid & 1) * 8;
    const int gq = lq >> 2;                 // 0 or 2
    const int bsw = (lm >> 1) & 1;          // granule swizzle bit
    const int pg0 = ((gq + bsw) & 3) * 4;
    const int pg1 = ((gq + 1 + bsw) & 3) * 4;
    const int bk = tid >> 5, bn = (tid & 31) * 4;

    float acc[4][4][4];
    #pragma unroll
    for (int mt = 0; mt < 4; mt++)
        #pragma unroll
        for (int nt = 0; nt < 4; nt++)
            #pragma unroll
            for (int r = 0; r < 4; r++) acc[mt][nt][r] = 0.f;

    auto cp_slab = [&](int k0, int st) {
        const float* gA = A + (size_t)(m0 + lm) * lda + k0 + lq;
        float* sA = &sm->fA[st][lm][0];
        cp16(sA + pg0, gA);
        cp16(sA + pg1, gA + 4);
        if (TB) {
            const float* gB = Bm + (size_t)(n0 + lm) * lda + k0 + lq;
            float* sB = &sm->fB[st][lm * 16];
            cp16(sB + pg0, gB);
            cp16(sB + pg1, gB + 4);
        } else {
            cp16(&sm->fB[st][(2 * bk) * 128 + bn],
                 Bm + (size_t)(k0 + 2 * bk) * Nn + n0 + bn);
            cp16(&sm->fB[st][(2 * bk + 1) * 128 + bn],
                 Bm + (size_t)(k0 + 2 * bk + 1) * Nn + n0 + bn);
        }
    };

    auto split_slab = [&](int st) {   // fp32 stage st -> bf16 stage st
        float a[8];
        const float* sA = &sm->fA[st][lm][0];
        *(float4*)(a)     = *(const float4*)(sA + pg0);
        *(float4*)(a + 4) = *(const float4*)(sA + pg1);
        #pragma unroll
        for (int j = 0; j < 4; j++) {
            unsigned hi, lo;
            split2(a[2 * j], a[2 * j + 1], hi, lo);
            sm->Ah[st][(lq >> 1) + j][lm] = hi;
            sm->Al[st][(lq >> 1) + j][lm] = lo;
        }
        if (TB) {
            float b[8];
            const float* sB = &sm->fB[st][lm * 16];
            *(float4*)(b)     = *(const float4*)(sB + pg0);
            *(float4*)(b + 4) = *(const float4*)(sB + pg1);
            #pragma unroll
            for (int j = 0; j < 4; j++) {
                unsigned hi, lo;
                split2(b[2 * j], b[2 * j + 1], hi, lo);
                sm->Bh[st][(lq >> 1) + j][lm] = hi;
                sm->Bl[st][(lq >> 1) + j][lm] = lo;
            }
        } else {
            float b[8];
            *(float4*)(b)     = *(const float4*)&sm->fB[st][(2 * bk) * 128 + bn];
            *(float4*)(b + 4) = *(const float4*)&sm->fB[st][(2 * bk + 1) * 128 + bn];
            #pragma unroll
            for (int j = 0; j < 4; j++) {
                unsigned hi, lo;
                split2(b[j], b[4 + j], hi, lo);
                sm->Bh[st][bk][bn + j] = hi;
                sm->Bl[st][bk][bn + j] = lo;
            }
        }
    };

    auto compute = [&](int st) {
        unsigned bh0[4], bh1[4], bl0[4], bl1[4];
        #pragma unroll
        for (int nt = 0; nt < 4; nt++) {
            int c = wn + nt * 8 + g;
            bh0[nt] = sm->Bh[st][tg][c];     bh1[nt] = sm->Bh[st][tg + 4][c];
            bl0[nt] = sm->Bl[st][tg][c];     bl1[nt] = sm->Bl[st][tg + 4][c];
        }
        #pragma unroll
        for (int mt = 0; mt < 4; mt++) {
            int r0c = wm + mt * 16 + g;
            unsigned ah0 = sm->Ah[st][tg][r0c],     ah1 = sm->Ah[st][tg][r0c + 8];
            unsigned ah2 = sm->Ah[st][tg + 4][r0c], ah3 = sm->Ah[st][tg + 4][r0c + 8];
            unsigned al0 = sm->Al[st][tg][r0c],     al1 = sm->Al[st][tg][r0c + 8];
            unsigned al2 = sm->Al[st][tg + 4][r0c], al3 = sm->Al[st][tg + 4][r0c + 8];
            #pragma unroll
            for (int nt = 0; nt < 4; nt++) {
                float* c = acc[mt][nt];
                mma_bf16(c, ah0, ah1, ah2, ah3, bh0[nt], bh1[nt]);
                mma_bf16(c, ah0, ah1, ah2, ah3, bl0[nt], bl1[nt]);
                mma_bf16(c, al0, al1, al2, al3, bh0[nt], bh1[nt]);
            }
        }
    };

    const int nslab = K >> 4;   // >= 2 always here
    cp_slab(0, 0);  cp_commit();
    cp_slab(16, 1); cp_commit();
    cp_wait<1>();               // slab 0 landed
    split_slab(0);
    __syncthreads();

    for (int kt = 0; kt < nslab; kt++) {
        const int st = kt & 1;
        if (kt + 2 < nslab) { cp_slab((kt + 2) << 4, st); cp_commit(); }
        compute(st);            // reads bf16 stage st
        if (kt + 1 < nslab) {
            if (kt + 2 < nslab) cp_wait<1>(); else cp_wait<0>();
            split_slab(st ^ 1); // writes bf16 stage st^1 (disjoint from compute's reads)
        }
        __syncthreads();
    }

    #pragma unroll
    for (int mt = 0; mt < 4; mt++) {
        int r0 = m0 + wm + mt * 16 + g;
        #pragma unroll
        for (int nt = 0; nt < 4; nt++) {
            int c0 = n0 + wn + nt * 8 + tg * 2;
            #pragma unroll
            for (int r = 0; r < 4; r++) {
                int mm = r0 + (r >> 1) * 8;
                int nn = c0 + (r & 1);
                float v = acc[mt][nt][r];
                if (EPI == EPI_BIAS || EPI == EPI_BIAS_GELU) v += bias[nn];
                if (EPI == EPI_BIAS_GELU) v = gelu_f(v);
                if (EPI == EPI_RES) v += res[(size_t)mm * Nn + nn];
                C[(size_t)mm * Nn + nn] = v;
            }
        }
    }
}

template<int EPI, bool TB>
__global__ void __launch_bounds__(256, 2) tgemm(
    const float* __restrict__ A, const float* __restrict__ Bm, float* __restrict__ C,
    int M, int Nn, int K, const float* __restrict__ bias, const float* __restrict__ res)
{
    tgemm_body<EPI, TB>(A, Bm, C, M, Nn, K, K, bias, res, blockIdx.y * 128, blockIdx.x * 128);
}

// split-K x2: blockIdx.z selects K-half; partial sums to C0 / C1 (summed in following LN)
template<bool TB>
__global__ void __launch_bounds__(256, 2) tgemm_sk(
    const float* __restrict__ A, const float* __restrict__ Bm,
    float* __restrict__ C0, float* __restrict__ C1,
    int M, int Nn, int Khalf, int lda)
{
    const int z = blockIdx.z;
    const float* Az = A + (size_t)z * Khalf;
    const float* Bz = TB ? (Bm + (size_t)z * Khalf) : (Bm + (size_t)z * Khalf * Nn);
    float* C = z ? C1 : C0;
    tgemm_body<EPI_NONE, TB>(Az, Bz, C, M, Nn, Khalf, lda, nullptr, nullptr,
                             blockIdx.y * 128, blockIdx.x * 128);
}

// merged projections: Wr (blocks 0..143), then Q,K,V (blocks 144..527)
__global__ void __launch_bounds__(256, 2) proj_all(
    const float* __restrict__ A, const float* __restrict__ pos_emb,
    const float* __restrict__ Wq, const float* __restrict__ Wk,
    const float* __restrict__ Wv, const float* __restrict__ Wr,
    float* __restrict__ Cq, float* __restrict__ Ck, float* __restrict__ Cv,
    float* __restrict__ Ckr)
{
    int idx = blockIdx.x;
    if (idx < 144) {
        tgemm_body<EPI_NONE, false>(pos_emb, Wr, Ckr, KRR * B_, ND, D_, D_, nullptr, nullptr,
                                    (idx >> 3) * 128, (idx & 7) * 128);
    } else {
        idx -= 144;
        int which = idx >> 7;     // 0..2
        int t = idx & 127;
        const float* Bm = (which == 0) ? Wq : (which == 1) ? Wk : Wv;
        float* C        = (which == 0) ? Cq : (which == 1) ? Ck : Cv;
        tgemm_body<EPI_NONE, false>(A, Bm, C, SB, ND, D_, D_, nullptr, nullptr,
                                    (t >> 3) * 128, (t & 7) * 128);
    }
}

// ---------------- ef[i,b,n,s] = (q + r_s_bias) . seg_embed[s] ----------------
__global__ void ef_kernel(const float* __restrict__ q, const float* __restrict__ rs,
                          const float* __restrict__ se, float* __restrict__ ef)
{
    int w = blockIdx.x * 4 + (threadIdx.x >> 5);   // over SB*NH
    int lane = threadIdx.x & 31;
    int row = w / NH, n = w % NH;
    int d0 = lane * 2;
    const float* qp = q + (size_t)row * ND + n * DH;
    float q0 = qp[d0]     + rs[n * DH + d0];
    float q1 = qp[d0 + 1] + rs[n * DH + d0 + 1];
    float s0 = q0 * se[(0 * NH + n) * DH + d0] + q1 * se[(0 * NH + n) * DH + d0 + 1];
    float s1 = q0 * se[(1 * NH + n) * DH + d0] + q1 * se[(1 * NH + n) * DH + d0 + 1];
    #pragma unroll
    for (int off = 16; off; off >>= 1) {
        s0 += __shfl_xor_sync(0xffffffffu, s0, off);
        s1 += __shfl_xor_sync(0xffffffffu, s1, off);
    }
    if (lane == 0) { ef[w * 2] = s0; ef[w * 2 + 1] = s1; }
}

// ---------------- fused flash attention: score + online softmax + P@V ----------------
struct FlashSmem {
    unsigned QA[4][32][72];                 // Qw hi/lo, Qr hi/lo [kpair][row]
    union {
        unsigned KB[2][32][200];            // hi/lo [kpair][col: 0..63 K, 64..191 Krs ring]
        float    ored[64][68];              // final O reduction
    } kb;
    float dloc[64][132];                    // Dloc table (logical u = lj-li+64)
    unsigned VB[2][32][72];                 // V hi/lo [kpair(j)][d]
    float ef_s[64][2];
    float redmax[64][4];
    float redl[64][4];
};

__global__ void __launch_bounds__(512, 1) flash_attn(
    const float* __restrict__ q, const float* __restrict__ k, const float* __restrict__ kr,
    const float* __restrict__ v,
    const float* __restrict__ rw, const float* __restrict__ rr,
    const float* __restrict__ ef, const float* __restrict__ seg_mat,
    float* __restrict__ vec)
{
    extern __shared__ char smraw[];
    FlashSmem* sm = (FlashSmem*)smraw;
    const int head = blockIdx.x;
    const int b = head / NH, n = head % NH;
    const int i0 = (15 - blockIdx.y) * 64;      // longest-running CTAs first
    const int tid = threadIdx.x;
    const int wid = tid >> 5, lane = tid & 31;
    const int g = lane >> 2, tg = lane & 3;
    const int rg = wid & 3, sub = wid >> 2;
    const int rbase = rg * 16;

    #pragma unroll
    for (int t = 0; t < 2; t++) {
        int job = tid + t * 512;
        int li = job >> 4, kq = (job & 15) * 4;
        const float* qp = q + ((size_t)((i0 + li) * B_ + b)) * ND + n * DH + kq;
        float4 qv = *(const float4*)qp;
        float4 wv = *(const float4*)(rw + n * DH + kq);
        float4 rv = *(const float4*)(rr + n * DH + kq);
        unsigned hi, lo; int kp = kq >> 1;
        split2(qv.x + wv.x, qv.y + wv.y, hi, lo); sm->QA[0][kp][li] = hi; sm->QA[1][kp][li] = lo;
        split2(qv.z + wv.z, qv.w + wv.w, hi, lo); sm->QA[0][kp+1][li] = hi; sm->QA[1][kp+1][li] = lo;
        split2(qv.x + rv.x, qv.y + rv.y, hi, lo); sm->QA[2][kp][li] = hi; sm->QA[3][kp][li] = lo;
        split2(qv.z + rv.z, qv.w + rv.w, hi, lo); sm->QA[2][kp+1][li] = hi; sm->QA[3][kp+1][li] = lo;
    }
    if (tid < 128)
        sm->ef_s[tid >> 1][tid & 1] =
            ef[((size_t)((i0 + (tid >> 1)) * B_ + b) * NH + n) * 2 + (tid & 1)];

    float m_r[2] = {-1e30f, -1e30f};
    float l_r[2] = {0.f, 0.f};
    float accO[8][4];
    #pragma unroll
    for (int f = 0; f < 8; f++)
        #pragma unroll
        for (int r = 0; r < 4; r++) accO[f][r] = 0.f;

    const int lK_li = tid >> 4, lK_dq = (tid & 15) * 4;   // K/Krs loaders
    const int lV_jp = tid >> 4, lV_dq = (tid & 15) * 4;   // V loader

    for (int j0 = 0; j0 <= i0; j0 += 64) {
        const int w = S_ + j0 - i0 - 64;        // ring window start (mult of 64)
        const int ofs = w & 127;
        const bool first = (j0 == 0);
        __syncthreads();   // previous iteration consumers done

        // ===== issue ALL gmem loads first =====
        float4 kv0 = *(const float4*)(k + ((size_t)((j0 + lK_li) * B_ + b)) * ND + n * DH + lK_dq);
        float4 kv1 = *(const float4*)(k + ((size_t)((j0 + lK_li + 32) * B_ + b)) * ND + n * DH + lK_dq);
        const float* vp0 = v + ((size_t)((j0 + 2 * lV_jp) * B_ + b)) * ND + n * DH + lV_dq;
        float4 vv0 = *(const float4*)vp0;
        float4 vv1 = *(const float4*)(vp0 + (size_t)B_ * ND);
        const int mstart = first ? w : (w + 64);
        float4 rv0 = *(const float4*)(kr + ((size_t)((mstart + lK_li) * B_ + b)) * ND + n * DH + lK_dq);
        float4 rv1 = *(const float4*)(kr + ((size_t)((mstart + lK_li + 32) * B_ + b)) * ND + n * DH + lK_dq);
        float4 rv2, rv3;
        if (first) {
            rv2 = *(const float4*)(kr + ((size_t)((mstart + lK_li + 64) * B_ + b)) * ND + n * DH + lK_dq);
            rv3 = *(const float4*)(kr + ((size_t)((mstart + lK_li + 96) * B_ + b)) * ND + n * DH + lK_dq);
        }
        float segv[2][4];
        #pragma unroll
        for (int fa = 0; fa < 2; fa++)
            #pragma unroll
            for (int r = 0; r < 4; r++) {
                int gi = i0 + rbase + g + (r >> 1) * 8;
                int gj = j0 + sub * 16 + fa * 8 + tg * 2 + (r & 1);
                segv[fa][r] = __ldg(&seg_mat[(((size_t)gi * S_ + gj) * B_ + b) * 2 + 1]);
            }

        // ===== split + store =====
        {
            unsigned hi, lo; int kp = lK_dq >> 1;
            split2(kv0.x, kv0.y, hi, lo); sm->kb.KB[0][kp][lK_li] = hi; sm->kb.KB[1][kp][lK_li] = lo;
            split2(kv0.z, kv0.w, hi, lo); sm->kb.KB[0][kp+1][lK_li] = hi; sm->kb.KB[1][kp+1][lK_li] = lo;
            split2(kv1.x, kv1.y, hi, lo); sm->kb.KB[0][kp][lK_li + 32] = hi; sm->kb.KB[1][kp][lK_li + 32] = lo;
            split2(kv1.z, kv1.w, hi, lo); sm->kb.KB[0][kp+1][lK_li + 32] = hi; sm->kb.KB[1][kp+1][lK_li + 32] = lo;
            int c0 = 64 + ((mstart + lK_li) & 127);
            int c1 = 64 + ((mstart + lK_li + 32) & 127);
            split2(rv0.x, rv0.y, hi, lo); sm->kb.KB[0][kp][c0] = hi; sm->kb.KB[1][kp][c0] = lo;
            split2(rv0.z, rv0.w, hi, lo); sm->kb.KB[0][kp+1][c0] = hi; sm->kb.KB[1][kp+1][c0] = lo;
            split2(rv1.x, rv1.y, hi, lo); sm->kb.KB[0][kp][c1] = hi; sm->kb.KB[1][kp][c1] = lo;
            split2(rv1.z, rv1.w, hi, lo); sm->kb.KB[0][kp+1][c1] = hi; sm->kb.KB[1][kp+1][c1] = lo;
            if (first) {
                int c2 = 64 + ((mstart + lK_li + 64) & 127);
                int c3 = 64 + ((mstart + lK_li + 96) & 127);
                split2(rv2.x, rv2.y, hi, lo); sm->kb.KB[0][kp][c2] = hi; sm->kb.KB[1][kp][c2] = lo;
                split2(rv2.z, rv2.w, hi, lo); sm->kb.KB[0][kp+1][c2] = hi; sm->kb.KB[1][kp+1][c2] = lo;
                split2(rv3.x, rv3.y, hi, lo); sm->kb.KB[0][kp][c3] = hi; sm->kb.KB[1][kp][c3] = lo;
                split2(rv3.z, rv3.w, hi, lo); sm->kb.KB[0][kp+1][c3] = hi; sm->kb.KB[1][kp+1][c3] = lo;
            }
            split2(vv0.x, vv1.x, hi, lo); sm->VB[0][lV_jp][lV_dq]     = hi; sm->VB[1][lV_jp][lV_dq]     = lo;
            split2(vv0.y, vv1.y, hi, lo); sm->VB[0][lV_jp][lV_dq + 1] = hi; sm->VB[1][lV_jp][lV_dq + 1] = lo;
            split2(vv0.z, vv1.z, hi, lo); sm->VB[0][lV_jp][lV_dq + 2] = hi; sm->VB[1][lV_jp][lV_dq + 2] = lo;
            split2(vv0.w, vv1.w, hi, lo); sm->VB[0][lV_jp][lV_dq + 3] = hi; sm->VB[1][lV_jp][lV_dq + 3] = lo;
        }
        __syncthreads();

        // --- score MMAs: ac (2 frags) + Dloc (4 frags) ---
        float aS[2][4], dS[4][4];
        #pragma unroll
        for (int f = 0; f < 2; f++)
            #pragma unroll
            for (int r = 0; r < 4; r++) aS[f][r] = 0.f;
        #pragma unroll
        for (int f = 0; f < 4; f++)
            #pragma unroll
            for (int r = 0; r < 4; r++) dS[f][r] = 0.f;

        #pragma unroll
        for (int kf = 0; kf < 4; kf++) {
            int kp = kf * 8;
            unsigned wh0 = sm->QA[0][kp + tg][rbase + g],     wh1 = sm->QA[0][kp + tg][rbase + g + 8];
            unsigned wh2 = sm->QA[0][kp + tg + 4][rbase + g], wh3 = sm->QA[0][kp + tg + 4][rbase + g + 8];
            unsigned wl0 = sm->QA[1][kp + tg][rbase + g],     wl1 = sm->QA[1][kp + tg][rbase + g + 8];
            unsigned wl2 = sm->QA[1][kp + tg + 4][rbase + g], wl3 = sm->QA[1][kp + tg + 4][rbase + g + 8];
            #pragma unroll
            for (int fa = 0; fa < 2; fa++) {
                int c = (sub * 2 + fa) * 8 + g;
                unsigned bh0 = sm->kb.KB[0][kp + tg][c], bh1 = sm->kb.KB[0][kp + tg + 4][c];
                unsigned bl0 = sm->kb.KB[1][kp + tg][c], bl1 = sm->kb.KB[1][kp + tg + 4][c];
                mma_bf16(aS[fa], wh0, wh1, wh2, wh3, bh0, bh1);
                mma_bf16(aS[fa], wh0, wh1, wh2, wh3, bl0, bl1);
                mma_bf16(aS[fa], wl0, wl1, wl2, wl3, bh0, bh1);
            }
            unsigned rh0 = sm->QA[2][kp + tg][rbase + g],     rh1 = sm->QA[2][kp + tg][rbase + g + 8];
            unsigned rh2 = sm->QA[2][kp + tg + 4][rbase + g], rh3 = sm->QA[2][kp + tg + 4][rbase + g + 8];
            unsigned rl0 = sm->QA[3][kp + tg][rbase + g],     rl1 = sm->QA[3][kp + tg][rbase + g + 8];
            unsigned rl2 = sm->QA[3][kp + tg + 4][rbase + g], rl3 = sm->QA[3][kp + tg + 4][rbase + g + 8];
            #pragma unroll
            for (int fd = 0; fd < 4; fd++) {
                int c = 64 + ((ofs + sub * 32 + fd * 8) & 127) + g;
                unsigned bh0 = sm->kb.KB[0][kp + tg][c], bh1 = sm->kb.KB[0][kp + tg + 4][c];
                unsigned bl0 = sm->kb.KB[1][kp + tg][c], bl1 = sm->kb.KB[1][kp + tg + 4][c];
                mma_bf16(dS[fd], rh0, rh1, rh2, rh3, bh0, bh1);
                mma_bf16(dS[fd], rh0, rh1, rh2, rh3, bl0, bl1);
                mma_bf16(dS[fd], rl0, rl1, rl2, rl3, bh0, bh1);
            }
        }
        #pragma unroll
        for (int fd = 0; fd < 4; fd++)
            #pragma unroll
            for (int r = 0; r < 4; r++)
                sm->dloc[rbase + g + (r >> 1) * 8][sub * 32 + fd * 8 + tg * 2 + (r & 1)] = dS[fd][r];
        __syncthreads();

        // --- combine + warp row max ---
        float s_v[2][4];
        float wmax[2] = {-3.0e38f, -3.0e38f};
        const bool diag = (j0 == i0);
        #pragma unroll
        for (int fa = 0; fa < 2; fa++)
            #pragma unroll
            for (int r = 0; r < 4; r++) {
                int li = rbase + g + (r >> 1) * 8;
                int lj = sub * 16 + fa * 8 + tg * 2 + (r & 1);
                float val;
                if (diag && lj > li) {
                    val = -1e30f;
                } else {
                    float dl = sm->dloc[li][lj - li + 64];
                    float e0 = sm->ef_s[li][0], e1 = sm->ef_s[li][1];
                    val = (aS[fa][r] + dl + e0 + segv[fa][r] * (e1 - e0)) * 0.125f;
                }
                s_v[fa][r] = val;
                wmax[r >> 1] = fmaxf(wmax[r >> 1], val);
            }
        #pragma unroll
        for (int hh = 0; hh < 2; hh++) {
            wmax[hh] = fmaxf(wmax[hh], __shfl_xor_sync(0xffffffffu, wmax[hh], 1));
            wmax[hh] = fmaxf(wmax[hh], __shfl_xor_sync(0xffffffffu, wmax[hh], 2));
        }
        if (tg == 0) {
            sm->redmax[rbase + g][sub]     = wmax[0];
            sm->redmax[rbase + g + 8][sub] = wmax[1];
        }
        __syncthreads();

        // --- online softmax update ---
        float alpha_h[2];
        #pragma unroll
        for (int hh = 0; hh < 2; hh++) {
            int li = rbase + g + hh * 8;
            float tm = fmaxf(fmaxf(sm->redmax[li][0], sm->redmax[li][1]),
                             fmaxf(sm->redmax[li][2], sm->redmax[li][3]));
            float mnew = fmaxf(m_r[hh], tm);
            alpha_h[hh] = __expf(m_r[hh] - mnew);
            m_r[hh] = mnew;
            l_r[hh] *= alpha_h[hh];
        }
        #pragma unroll
        for (int f = 0; f < 8; f++) {
            accO[f][0] *= alpha_h[0]; accO[f][1] *= alpha_h[0];
            accO[f][2] *= alpha_h[1]; accO[f][3] *= alpha_h[1];
        }
        float pv[2][4];
        float psum[2] = {0.f, 0.f};
        #pragma unroll
        for (int fa = 0; fa < 2; fa++)
            #pragma unroll
            for (int r = 0; r < 4; r++) {
                float p = __expf(s_v[fa][r] - m_r[r >> 1]);
                pv[fa][r] = p;
                psum[r >> 1] += p;
            }
        #pragma unroll
        for (int hh = 0; hh < 2; hh++) {
            psum[hh] += __shfl_xor_sync(0xffffffffu, psum[hh], 1);
            psum[hh] += __shfl_xor_sync(0xffffffffu, psum[hh], 2);
            l_r[hh] += psum[hh];
        }
        unsigned ph[4], pl[4];
        split2(pv[0][0], pv[0][1], ph[0], pl[0]);
        split2(pv[0][2], pv[0][3], ph[1], pl[1]);
        split2(pv[1][0], pv[1][1], ph[2], pl[2]);
        split2(pv[1][2], pv[1][3], ph[3], pl[3]);
        const int kpb = sub * 8;
        #pragma unroll
        for (int f = 0; f < 8; f++) {
            int c = f * 8 + g;
            unsigned bh0 = sm->VB[0][kpb + tg][c], bh1 = sm->VB[0][kpb + tg + 4][c];
            unsigned bl0 = sm->VB[1][kpb + tg][c], bl1 = sm->VB[1][kpb + tg + 4][c];
            mma_bf16(accO[f], ph[0], ph[1], ph[2], ph[3], bh0, bh1);
            mma_bf16(accO[f], ph[0], ph[1], ph[2], ph[3], bl0, bl1);
            mma_bf16(accO[f], pl[0], pl[1], pl[2], pl[3], bh0, bh1);
        }
    }

    // --- final: reduce K-split partials deterministically, normalize, store ---
    __syncthreads();
    if (tg == 0) {
        sm->redl[rbase + g][sub]     = l_r[0];
        sm->redl[rbase + g + 8][sub] = l_r[1];
    }
    #pragma unroll
    for (int s = 0; s < 4; s++) {
        if (sub == s) {
            #pragma unroll
            for (int f = 0; f < 8; f++)
                #pragma unroll
                for (int r = 0; r < 4; r++) {
                    int row = rbase + g + (r >> 1) * 8;
                    int col = f * 8 + tg * 2 + (r & 1);
                    if (s == 0) sm->kb.ored[row][col] = accO[f][r];
                    else        sm->kb.ored[row][col] += accO[f][r];
                }
        }
        __syncthreads();
    }
    #pragma unroll
    for (int t = 0; t < 8; t++) {
        int job = tid + t * 512;
        int row = job >> 6, col = job & 63;
        float lt = sm->redl[row][0] + sm->redl[row][1] + sm->redl[row][2] + sm->redl[row][3];
        vec[((size_t)((i0 + row) * B_ + b)) * ND + n * DH + col] = sm->kb.ored[row][col] / lt;
    }
}

// ---------------- layernorm: LN(x + r1? + r2? + bias?) ----------------
__global__ void ln_kernel(const float* __restrict__ x, const float* __restrict__ r1,
                          const float* __restrict__ r2, const float* __restrict__ bias,
                          const float* __restrict__ g, const float* __restrict__ b,
                          float* __restrict__ out)
{
    __shared__ float red[256];
    const int row = blockIdx.x, tid = threadIdx.x;
    const float* xr = x + (size_t)row * D_;
    float v[4];
    float s = 0.f;
    #pragma unroll
    for (int t = 0; t < 4; t++) {
        int d = tid + t * 256;
        v[t] = xr[d];
        if (r1)   v[t] += r1[(size_t)row * D_ + d];
        if (r2)   v[t] += r2[(size_t)row * D_ + d];
        if (bias) v[t] += bias[d];
        s += v[t];
    }
    red[tid] = s; __syncthreads();
    for (int o = 128; o > 0; o >>= 1) { if (tid < o) red[tid] += red[tid + o]; __syncthreads(); }
    float mean = red[0] * (1.f / D_);
    __syncthreads();
    s = 0.f;
    #pragma unroll
    for (int t = 0; t < 4; t++) { float d2 = v[t] - mean; s += d2 * d2; }
    red[tid] = s; __syncthreads();
    for (int o = 128; o > 0; o >>= 1) { if (tid < o) red[tid] += red[tid + o]; __syncthreads(); }
    float inv = rsqrtf(red[0] * (1.f / D_) + 1e-12f);
    #pragma unroll
    for (int t = 0; t < 4; t++) {
        int d = tid + t * 256;
        out[(size_t)row * D_ + d] = (v[t] - mean) * inv * g[d] + b[d];
    }
}

// ---------------- host ----------------
static float* sym_addr(const void* sym) {
    void* p = nullptr;
    cudaGetSymbolAddress(&p, sym);
    return (float*)p;
}

extern "C" void kernel_launch(void* const* d_in, const int* in_sizes, int n_in,
                              void* d_out, int out_size)
{
    (void)in_sizes; (void)n_in; (void)out_size;
    const float* h         = (const float*)d_in[0];
    const float* pos_emb   = (const float*)d_in[1];
    const float* seg_mat   = (const float*)d_in[3];
    const float* Wq        = (const float*)d_in[4];
    const float* Wk        = (const float*)d_in[5];
    const float* Wv        = (const float*)d_in[6];
    const float* Wo        = (const float*)d_in[7];
    const float* Wr        = (const float*)d_in[8];
    const float* rw        = (const float*)d_in[9];
    const float* rr        = (const float*)d_in[10];
    const float* rs        = (const float*)d_in[11];
    const float* se        = (const float*)d_in[12];
    const float* ln1g      = (const float*)d_in[13];
    const float* ln1b      = (const float*)d_in[14];
    const float* w1        = (const float*)d_in[15];
    const float* b1        = (const float*)d_in[16];
    const float* w2        = (const float*)d_in[17];
    const float* b2        = (const float*)d_in[18];
    const float* ln2g      = (const float*)d_in[19];
    const float* ln2b      = (const float*)d_in[20];
    float* out = (float*)d_out;

    float* gq    = sym_addr(g_q);
    float* gk    = sym_addr(g_k);
    float* gv    = sym_addr(g_v);
    float* gkr   = sym_addr(g_kr);
    float* gef   = sym_addr(g_ef);
    float* gvec  = sym_addr(g_vec);
    float* gattn = sym_addr(g_attn);
    float* gp1   = sym_addr(g_p1);
    float* gx    = sym_addr(g_x);
    float* gf    = sym_addr(g_f);
    float* gf2   = sym_addr(g_f2);
    float* gbuf  = sym_addr(g_buf);

    const int GS = (int)sizeof(GemmSmem);
    static bool attr_set = false;
    if (!attr_set) {
        cudaFuncSetAttribute(flash_attn, cudaFuncAttributeMaxDynamicSharedMemorySize,
                             (int)sizeof(FlashSmem));
        cudaFuncSetAttribute(proj_all, cudaFuncAttributeMaxDynamicSharedMemorySize, GS);
        cudaFuncSetAttribute(tgemm_sk<true>,  cudaFuncAttributeMaxDynamicSharedMemorySize, GS);
        cudaFuncSetAttribute(tgemm_sk<false>, cudaFuncAttributeMaxDynamicSharedMemorySize, GS);
        cudaFuncSetAttribute(tgemm<EPI_BIAS_GELU, false>, cudaFuncAttributeMaxDynamicSharedMemorySize, GS);
        attr_set = true;
    }

    for (int l = 0; l < 2; l++) {
        const float* cur = (l == 0) ? h : gbuf;
        float* nxt = (l == 0) ? gbuf : out;
        const size_t woff = (size_t)l * D_ * ND;

        proj_all<<<144 + 384, 256, GS>>>(
            cur, pos_emb, Wq + woff, Wk + woff, Wv + woff, Wr + woff,
            gq, gk, gv, gkr);

        ef_kernel<<<SB * NH / 4, 128>>>(gq, rs + l * NH * DH, se + l * 2 * NH * DH, gef);

        flash_attn<<<dim3(NHEADS, S_ / 64), 512, sizeof(FlashSmem)>>>(
            gq, gk, gkr, gv, rw + l * NH * DH, rr + l * NH * DH,
            gef, seg_mat, gvec);

        // Wo: vec[SB,ND] @ Wo^T[ND->D], split-K x2 (partials summed in ln1)
        tgemm_sk<true><<<dim3(D_ / 128, SB / 128, 2), 256, GS>>>(
            gvec, Wo + woff, gattn, gp1, SB, D_, ND / 2, ND);

        // ln1: LN(part0 + part1 + residual)
        ln_kernel<<<SB, 256>>>(gattn, gp1, cur, nullptr, ln1g + l * D_, ln1b + l * D_, gx);

        tgemm<EPI_BIAS_GELU, false><<<dim3(DI_ / 128, SB / 128), 256, GS>>>(
            gx, w1 + (size_t)l * D_ * DI_, gf, SB, DI_, D_, b1 + l * DI_, nullptr);

        // FFN2: f[SB,DI] @ w2[DI->D], split-K x2 (partials + bias summed in ln2)
        tgemm_sk<false><<<dim3(D_ / 128, SB / 128, 2), 256, GS>>>(
            gf, w2 + (size_t)l * DI_ * D_, gf2, gp1, SB, D_, DI_ / 2, DI_);

        // ln2: LN(part0 + part1 + b2 + x)
        ln_kernel<<<SB, 256>>>(gf2, gp1, gx, b2 + l * D_, ln2g + l * D_, ln2b + l * D_, nxt);
    }
}